// round 1
// baseline (speedup 1.0000x reference)
#include <cuda_runtime.h>
#include <math.h>
#include <float.h>

#define Bb   4
#define Nn   1024
#define DIMm 1024
#define Hh   16
#define DHh  64
#define Mm   16
#define NJ   1040          // M + N
#define ROWS 4096          // B*N
#define QK_SCALE 10.0f

// ---------------- scratch (device globals: sanctioned scratch mechanism) ----
__device__ float g_Qraw[(size_t)ROWS * DIMm];
__device__ float g_Kraw[(size_t)ROWS * DIMm];
__device__ float g_Vraw[(size_t)ROWS * DIMm];
__device__ float g_vgraw[(size_t)ROWS * DIMm];
__device__ float g_hgraw[(size_t)ROWS * Hh];
__device__ float g_Qp[(size_t)Bb * Hh * Nn * DHh];
__device__ float g_Kp[(size_t)Bb * Hh * NJ * DHh];
__device__ float g_Vp[(size_t)Bb * Hh * NJ * DHh];
__device__ float g_dots[(size_t)Bb * Hh * Nn * NJ];   // reused in-place for attn2
__device__ float g_outg[(size_t)ROWS * DIMm];

// ---------------- generic fp32 GEMM: C[ROWS x Nw] = A[ROWS x K] @ W[K x Nw] --
__global__ void gemm_xw(const float* __restrict__ A, const float* __restrict__ W,
                        float* __restrict__ C, int K, int Nw) {
    __shared__ __align__(16) float XsT[16][68];
    __shared__ __align__(16) float Ws[16][64];
    int t = threadIdx.x;
    int i0 = blockIdx.y * 64, n0 = blockIdx.x * 64;
    int tx = t & 15, ty = t >> 4;
    float acc[4][4] = {};
    for (int k0 = 0; k0 < K; k0 += 16) {
        {
            int row = t >> 2, c4 = (t & 3) * 4;
            float4 v = *(const float4*)&A[(size_t)(i0 + row) * K + k0 + c4];
            XsT[c4 + 0][row] = v.x; XsT[c4 + 1][row] = v.y;
            XsT[c4 + 2][row] = v.z; XsT[c4 + 3][row] = v.w;
        }
        {
            int row = t >> 4, c4 = (t & 15) * 4;
            *(float4*)&Ws[row][c4] = *(const float4*)&W[(size_t)(k0 + row) * Nw + n0 + c4];
        }
        __syncthreads();
#pragma unroll
        for (int kk = 0; kk < 16; kk++) {
            float4 a = *(const float4*)&XsT[kk][ty * 4];
            float4 b = *(const float4*)&Ws[kk][tx * 4];
            float av[4] = {a.x, a.y, a.z, a.w};
            float bv[4] = {b.x, b.y, b.z, b.w};
#pragma unroll
            for (int u = 0; u < 4; u++)
#pragma unroll
                for (int v2 = 0; v2 < 4; v2++) acc[u][v2] += av[u] * bv[v2];
        }
        __syncthreads();
    }
#pragma unroll
    for (int u = 0; u < 4; u++) {
        float4 o = {acc[u][0], acc[u][1], acc[u][2], acc[u][3]};
        *(float4*)&C[(size_t)(i0 + ty * 4 + u) * Nw + n0 + tx * 4] = o;
    }
}

// ---------------- head-gate GEMM: C[ROWS x 16] = A @ W[1024 x 16] -----------
__global__ void gemm_hgate(const float* __restrict__ A, const float* __restrict__ W) {
    __shared__ __align__(16) float XsT[16][68];
    __shared__ float Ws[16][16];
    int t = threadIdx.x;
    int i0 = blockIdx.x * 64;
    int tx = t & 15, ty = t >> 4;
    float acc[4] = {};
    for (int k0 = 0; k0 < DIMm; k0 += 16) {
        {
            int row = t >> 2, c4 = (t & 3) * 4;
            float4 v = *(const float4*)&A[(size_t)(i0 + row) * DIMm + k0 + c4];
            XsT[c4 + 0][row] = v.x; XsT[c4 + 1][row] = v.y;
            XsT[c4 + 2][row] = v.z; XsT[c4 + 3][row] = v.w;
        }
        Ws[t >> 4][t & 15] = W[(size_t)(k0 + (t >> 4)) * Hh + (t & 15)];
        __syncthreads();
#pragma unroll
        for (int kk = 0; kk < 16; kk++) {
            float4 a = *(const float4*)&XsT[kk][ty * 4];
            float w = Ws[kk][tx];
            acc[0] += a.x * w; acc[1] += a.y * w;
            acc[2] += a.z * w; acc[3] += a.w * w;
        }
        __syncthreads();
    }
#pragma unroll
    for (int u = 0; u < 4; u++)
        g_hgraw[(size_t)(i0 + ty * 4 + u) * Hh + tx] = acc[u];
}

// ---------------- l2norm + scale + rope + layout; mem-kv prep --------------
__global__ void prep_kernel(const float* __restrict__ freqs,
                            const float* __restrict__ q_scale,
                            const float* __restrict__ k_scale,
                            const float* __restrict__ mem_k,
                            const float* __restrict__ mem_v) {
    int w = (blockIdx.x * blockDim.x + threadIdx.x) >> 5;
    int lane = threadIdx.x & 31;
    const int MAIN = Bb * Nn * Hh;
    if (w < MAIN) {
        int b = w / (Nn * Hh); int r = w % (Nn * Hh);
        int n = r / Hh; int h = r % Hh;
        size_t src = (size_t)(b * Nn + n) * DIMm + h * DHh;
        float2 q2 = ((const float2*)&g_Qraw[src])[lane];
        float2 k2 = ((const float2*)&g_Kraw[src])[lane];
        float2 v2 = ((const float2*)&g_Vraw[src])[lane];
        float ssq = q2.x * q2.x + q2.y * q2.y;
        float ssk = k2.x * k2.x + k2.y * k2.y;
        for (int o = 16; o > 0; o >>= 1) {
            ssq += __shfl_xor_sync(~0u, ssq, o);
            ssk += __shfl_xor_sync(~0u, ssk, o);
        }
        float invq = 1.0f / fmaxf(sqrtf(ssq), 1e-12f);
        float invk = 1.0f / fmaxf(sqrtf(ssk), 1e-12f);
        float sqx = q_scale[h * DHh + 2 * lane], sqy = q_scale[h * DHh + 2 * lane + 1];
        float skx = k_scale[h * DHh + 2 * lane], sky = k_scale[h * DHh + 2 * lane + 1];
        float qx = q2.x * invq * sqx, qy = q2.y * invq * sqy;
        float kx = k2.x * invk * skx, ky = k2.y * invk * sky;
        float f = freqs[n * DHh + 2 * lane];
        float cf = cosf(f), sf = sinf(f);
        float2 qo = {qx * cf - qy * sf, qy * cf + qx * sf};
        float2 ko = {kx * cf - ky * sf, ky * cf + kx * sf};
        ((float2*)&g_Qp[((size_t)(b * Hh + h) * Nn + n) * DHh])[lane] = qo;
        ((float2*)&g_Kp[((size_t)(b * Hh + h) * NJ + Mm + n) * DHh])[lane] = ko;
        ((float2*)&g_Vp[((size_t)(b * Hh + h) * NJ + Mm + n) * DHh])[lane] = v2;
    } else {
        int w2 = w - MAIN;
        if (w2 < Bb * Hh * Mm) {
            int b = w2 / (Hh * Mm); int r = w2 % (Hh * Mm);
            int h = r / Mm; int m = r % Mm;
            float2 mk = ((const float2*)&mem_k[(size_t)(h * Mm + m) * DHh])[lane];
            float2 mv = ((const float2*)&mem_v[(size_t)(h * Mm + m) * DHh])[lane];
            float ss = mk.x * mk.x + mk.y * mk.y;
            for (int o = 16; o > 0; o >>= 1) ss += __shfl_xor_sync(~0u, ss, o);
            float inv = 1.0f / fmaxf(sqrtf(ss), 1e-12f);
            float2 ko = {mk.x * inv * k_scale[h * DHh + 2 * lane],
                         mk.y * inv * k_scale[h * DHh + 2 * lane + 1]};
            ((float2*)&g_Kp[((size_t)(b * Hh + h) * NJ + m) * DHh])[lane] = ko;
            ((float2*)&g_Vp[((size_t)(b * Hh + h) * NJ + m) * DHh])[lane] = mv;
        }
    }
}

// ---------------- dots[b,h] = Qp[b,h] @ Kp[b,h]^T * QK_SCALE ---------------
__global__ void dots_kernel() {
    int bh = blockIdx.z;
    int i0 = blockIdx.y * 64;
    int j0 = blockIdx.x * 64;
    if (j0 >= i0 + 80) return;      // entire tile causally masked
    __shared__ __align__(16) float QsT[64][68];
    __shared__ __align__(16) float KsT[64][68];
    int t = threadIdx.x;
    const float* Q = &g_Qp[(size_t)bh * Nn * DHh];
    const float* Kk = &g_Kp[(size_t)bh * NJ * DHh];
#pragma unroll
    for (int s = 0; s < 4; s++) {
        int f = t + s * 256;
        int row = f >> 4, c4 = (f & 15) * 4;
        float4 v = *(const float4*)&Q[(size_t)(i0 + row) * DHh + c4];
        QsT[c4 + 0][row] = v.x; QsT[c4 + 1][row] = v.y;
        QsT[c4 + 2][row] = v.z; QsT[c4 + 3][row] = v.w;
    }
#pragma unroll
    for (int s = 0; s < 4; s++) {
        int f = t + s * 256;
        int row = f >> 4, c4 = (f & 15) * 4;   // row = j-local
        float4 v = make_float4(0.f, 0.f, 0.f, 0.f);
        if (j0 + row < NJ) v = *(const float4*)&Kk[(size_t)(j0 + row) * DHh + c4];
        KsT[c4 + 0][row] = v.x; KsT[c4 + 1][row] = v.y;
        KsT[c4 + 2][row] = v.z; KsT[c4 + 3][row] = v.w;
    }
    __syncthreads();
    int tx = t & 15, ty = t >> 4;
    float acc[4][4] = {};
#pragma unroll 8
    for (int d = 0; d < 64; d++) {
        float4 a = *(const float4*)&QsT[d][ty * 4];
        float4 b = *(const float4*)&KsT[d][tx * 4];
        float av[4] = {a.x, a.y, a.z, a.w};
        float bv[4] = {b.x, b.y, b.z, b.w};
#pragma unroll
        for (int u = 0; u < 4; u++)
#pragma unroll
            for (int v2 = 0; v2 < 4; v2++) acc[u][v2] += av[u] * bv[v2];
    }
    if (j0 + tx * 4 < NJ) {
#pragma unroll
        for (int u = 0; u < 4; u++) {
            float4 o = {acc[u][0] * QK_SCALE, acc[u][1] * QK_SCALE,
                        acc[u][2] * QK_SCALE, acc[u][3] * QK_SCALE};
            *(float4*)&g_dots[((size_t)bh * Nn + i0 + ty * 4 + u) * NJ + j0 + tx * 4] = o;
        }
    }
}

// ------- fused: pre-mix (W_pre) -> per-head softmax -> post-mix (W_post) ----
// CTA per (b, i); in-place on g_dots (reads all h of row i, then writes all g)
__global__ void softmax_kernel(const float* __restrict__ W_pre,
                               const float* __restrict__ W_post) {
    extern __shared__ float smem[];
    float* sD = smem;                 // 16 * NJ
    float* sT = sD + 16 * NJ;         // 16 * 64 staging
    float* sWpre = sT + 16 * 64;      // 256
    float* sWpost = sWpre + 256;      // 256
    int t = threadIdx.x;
    int i = blockIdx.x, b = blockIdx.y;
    sWpre[t] = W_pre[t];
    sWpost[t] = W_post[t];
    int jcount = i + 17;              // visible: j <= i + 16
    __syncthreads();
    int g = t >> 4, q = t & 15;
    for (int j0 = 0; j0 < jcount; j0 += 64) {
        for (int idx = t; idx < 1024; idx += 256) {
            int h = idx >> 6, jj = idx & 63, j = j0 + jj;
            sT[idx] = (j < jcount)
                ? g_dots[((size_t)(b * Hh + h) * Nn + i) * NJ + j] : 0.f;
        }
        __syncthreads();
#pragma unroll
        for (int u = 0; u < 4; u++) {
            int jj = q * 4 + u, j = j0 + jj;
            if (j < jcount) {
                float a = 0.f;
#pragma unroll
                for (int h = 0; h < 16; h++) a += sWpre[g * 16 + h] * sT[h * 64 + jj];
                sD[g * NJ + j] = a;
            }
        }
        __syncthreads();
    }
    // per-head softmax over valid range
    int warp = t >> 5, lane = t & 31;
    for (int gg = warp; gg < 16; gg += 8) {
        float* row = sD + gg * NJ;
        float m = -FLT_MAX;
        for (int j = lane; j < jcount; j += 32) m = fmaxf(m, row[j]);
        for (int o = 16; o > 0; o >>= 1) m = fmaxf(m, __shfl_xor_sync(~0u, m, o));
        float l = 0.f;
        for (int j = lane; j < jcount; j += 32) {
            float e = expf(row[j] - m); row[j] = e; l += e;
        }
        for (int o = 16; o > 0; o >>= 1) l += __shfl_xor_sync(~0u, l, o);
        float inv = 1.f / l;
        for (int j = lane; j < jcount; j += 32) row[j] *= inv;
    }
    __syncthreads();
    // post-mix, write back (zeros in the diagonal band beyond jcount)
    int i0 = i & ~63;
    int jend = min(NJ, i0 + 128);
    for (int j0 = 0; j0 < jend; j0 += 64) {
        float vals[4];
#pragma unroll
        for (int u = 0; u < 4; u++) {
            int j = j0 + q * 4 + u;
            float a = 0.f;
            if (j < jcount) {
#pragma unroll
                for (int h = 0; h < 16; h++) a += sWpost[g * 16 + h] * sD[h * NJ + j];
            }
            vals[u] = a;
        }
        int j = j0 + q * 4;
        if (j < jend) {
            float4 o = {vals[0], vals[1], vals[2], vals[3]};
            *(float4*)&g_dots[((size_t)(b * Hh + g) * Nn + i) * NJ + j] = o;
        }
    }
}

// ------- out[b,g] = attn2[b,g] @ Vp[b,g], fused head+value gates -----------
__global__ void av_kernel(const float* __restrict__ b_hgate,
                          const float* __restrict__ b_vgate) {
    int bg = blockIdx.y;              // b*16 + g
    int i0 = blockIdx.x * 64;
    int jlimit = min(NJ, i0 + 128);
    __shared__ __align__(16) float AsT[64][68];
    __shared__ __align__(16) float Vs[64][68];
    int t = threadIdx.x, tx = t & 15, ty = t >> 4;
    float acc[4][4] = {};
    const float* attn = &g_dots[(size_t)bg * Nn * NJ];
    const float* V = &g_Vp[(size_t)bg * NJ * DHh];
    for (int j0 = 0; j0 < jlimit; j0 += 64) {
#pragma unroll
        for (int s = 0; s < 4; s++) {
            int f = t + s * 256;
            int row = f >> 4, c4 = (f & 15) * 4;   // row=i-local, c4=j-local
            float4 v = make_float4(0.f, 0.f, 0.f, 0.f);
            if (j0 + c4 < NJ) v = *(const float4*)&attn[(size_t)(i0 + row) * NJ + j0 + c4];
            AsT[c4 + 0][row] = v.x; AsT[c4 + 1][row] = v.y;
            AsT[c4 + 2][row] = v.z; AsT[c4 + 3][row] = v.w;
        }
#pragma unroll
        for (int s = 0; s < 4; s++) {
            int f = t + s * 256;
            int jr = f >> 4, c4 = (f & 15) * 4;    // jr=j-local, c4=d
            float4 v = make_float4(0.f, 0.f, 0.f, 0.f);
            if (j0 + jr < NJ) v = *(const float4*)&V[(size_t)(j0 + jr) * DHh + c4];
            *(float4*)&Vs[jr][c4] = v;
        }
        __syncthreads();
#pragma unroll 8
        for (int jj = 0; jj < 64; jj++) {
            float4 a = *(const float4*)&AsT[jj][ty * 4];
            float4 bb = *(const float4*)&Vs[jj][tx * 4];
            float av[4] = {a.x, a.y, a.z, a.w};
            float bv[4] = {bb.x, bb.y, bb.z, bb.w};
#pragma unroll
            for (int u = 0; u < 4; u++)
#pragma unroll
                for (int v2 = 0; v2 < 4; v2++) acc[u][v2] += av[u] * bv[v2];
        }
        __syncthreads();
    }
    int b = bg >> 4, g = bg & 15;
#pragma unroll
    for (int u = 0; u < 4; u++) {
        int i = i0 + ty * 4 + u;
        size_t rbase = (size_t)(b * Nn + i);
        float hg = 1.f / (1.f + expf(-(g_hgraw[rbase * Hh + g] + b_hgate[g])));
#pragma unroll
        for (int v2 = 0; v2 < 4; v2++) {
            int d = tx * 4 + v2;
            float vgv = 1.f / (1.f + expf(-(g_vgraw[rbase * DIMm + g * DHh + d] +
                                            b_vgate[g * DHh + d])));
            g_outg[rbase * DIMm + g * DHh + d] = acc[u][v2] * hg * vgv;
        }
    }
}

// ---------------------------------------------------------------------------
extern "C" void kernel_launch(void* const* d_in, const int* in_sizes, int n_in,
                              void* d_out, int out_size) {
    const float* x       = (const float*)d_in[0];
    const float* freqs   = (const float*)d_in[1];
    const float* Wq      = (const float*)d_in[2];
    const float* Wk      = (const float*)d_in[3];
    const float* Wv      = (const float*)d_in[4];
    const float* q_scale = (const float*)d_in[5];
    const float* k_scale = (const float*)d_in[6];
    const float* mem_k   = (const float*)d_in[7];
    const float* mem_v   = (const float*)d_in[8];
    const float* W_pre   = (const float*)d_in[9];
    const float* W_post  = (const float*)d_in[10];
    const float* W_hgate = (const float*)d_in[11];
    const float* b_hgate = (const float*)d_in[12];
    const float* W_vgate = (const float*)d_in[13];
    const float* b_vgate = (const float*)d_in[14];
    const float* Wo      = (const float*)d_in[15];
    float* out = (float*)d_out;

    float *Qraw, *Kraw, *Vraw, *vgraw, *outg;
    cudaGetSymbolAddress((void**)&Qraw, g_Qraw);
    cudaGetSymbolAddress((void**)&Kraw, g_Kraw);
    cudaGetSymbolAddress((void**)&Vraw, g_Vraw);
    cudaGetSymbolAddress((void**)&vgraw, g_vgraw);
    cudaGetSymbolAddress((void**)&outg, g_outg);

    dim3 gW(DIMm / 64, ROWS / 64);
    gemm_xw<<<gW, 256>>>(x, Wq, Qraw, DIMm, DIMm);
    gemm_xw<<<gW, 256>>>(x, Wk, Kraw, DIMm, DIMm);
    gemm_xw<<<gW, 256>>>(x, Wv, Vraw, DIMm, DIMm);
    gemm_xw<<<gW, 256>>>(x, W_vgate, vgraw, DIMm, DIMm);
    gemm_hgate<<<ROWS / 64, 256>>>(x, W_hgate);

    int warps = Bb * Nn * Hh + Bb * Hh * Mm;
    prep_kernel<<<(warps + 7) / 8, 256>>>(freqs, q_scale, k_scale, mem_k, mem_v);

    dots_kernel<<<dim3((NJ + 63) / 64, Nn / 64, Bb * Hh), 256>>>();

    size_t smem_bytes = (16 * NJ + 16 * 64 + 512) * sizeof(float);  // ~72.7 KB
    cudaFuncSetAttribute(softmax_kernel, cudaFuncAttributeMaxDynamicSharedMemorySize,
                         (int)smem_bytes);
    softmax_kernel<<<dim3(Nn, Bb), 256, smem_bytes>>>(W_pre, W_post);

    av_kernel<<<dim3(Nn / 64, Bb * Hh), 256>>>(b_hgate, b_vgate);

    gemm_xw<<<gW, 256>>>(outg, Wo, out, DIMm, DIMm);
}

// round 3
// speedup vs baseline: 2.6338x; 2.6338x over previous
#include <cuda_runtime.h>
#include <cuda_bf16.h>
#include <math.h>
#include <float.h>
#include <stdint.h>

#define Bb   4
#define Nn   1024
#define DIMm 1024
#define Hh   16
#define DHh  64
#define Mm   16
#define NJ   1040          // M + N
#define ROWS 4096          // B*N
#define QK_SCALE 10.0f

// ===================== scratch =============================================
__device__ float g_Qraw[(size_t)ROWS * DIMm];
__device__ float g_Kraw[(size_t)ROWS * DIMm];
__device__ float g_Vraw[(size_t)ROWS * DIMm];
__device__ float g_vgraw[(size_t)ROWS * DIMm];
__device__ float g_hgraw[(size_t)ROWS * Hh];
__device__ float g_Qp[(size_t)Bb * Hh * Nn * DHh];
__device__ float g_Kp[(size_t)Bb * Hh * NJ * DHh];
__device__ float g_Vp[(size_t)Bb * Hh * NJ * DHh];
__device__ float g_dots[(size_t)Bb * Hh * Nn * NJ];
__device__ float g_outg[(size_t)ROWS * DIMm];
__device__ __nv_bfloat16 g_Ahi[(size_t)ROWS * DIMm];
__device__ __nv_bfloat16 g_Alo[(size_t)ROWS * DIMm];
__device__ __nv_bfloat16 g_Wthi[(size_t)5 * DIMm * DIMm];
__device__ __nv_bfloat16 g_Wtlo[(size_t)5 * DIMm * DIMm];

// ===================== PTX helpers (base ISA only) =========================
__device__ __forceinline__ uint32_t smem_u32(const void* p) {
    uint32_t a;
    asm("{ .reg .u64 tmp; cvta.to.shared.u64 tmp, %1; cvt.u32.u64 %0, tmp; }"
        : "=r"(a) : "l"(p));
    return a;
}
__device__ __forceinline__ void cp_async16(uint32_t s, const void* g) {
    asm volatile("cp.async.cg.shared.global [%0], [%1], 16;" :: "r"(s), "l"(g));
}
__device__ __forceinline__ void cp_commit() {
    asm volatile("cp.async.commit_group;" ::: "memory");
}
__device__ __forceinline__ void cp_wait1() {
    asm volatile("cp.async.wait_group 1;" ::: "memory");
}
__device__ __forceinline__ void cp_wait0() {
    asm volatile("cp.async.wait_group 0;" ::: "memory");
}
__device__ __forceinline__ void ldsm_x4(uint32_t* r, uint32_t addr) {
    asm volatile("ldmatrix.sync.aligned.m8n8.x4.shared.b16 {%0,%1,%2,%3}, [%4];"
                 : "=r"(r[0]), "=r"(r[1]), "=r"(r[2]), "=r"(r[3]) : "r"(addr));
}
__device__ __forceinline__ void mma16816(float* d, const uint32_t* a, const uint32_t* b) {
    asm volatile(
        "mma.sync.aligned.m16n8k16.row.col.f32.bf16.bf16.f32 "
        "{%0,%1,%2,%3}, {%4,%5,%6,%7}, {%8,%9}, {%0,%1,%2,%3};"
        : "+f"(d[0]), "+f"(d[1]), "+f"(d[2]), "+f"(d[3])
        : "r"(a[0]), "r"(a[1]), "r"(a[2]), "r"(a[3]), "r"(b[0]), "r"(b[1]));
}

// ===================== convert kernels =====================================
__global__ void conv_hilo(const float* __restrict__ src,
                          __nv_bfloat16* __restrict__ hi,
                          __nv_bfloat16* __restrict__ lo) {
    int i = blockIdx.x * 256 + threadIdx.x;
    float4 v = ((const float4*)src)[i];
    float f[4] = {v.x, v.y, v.z, v.w};
    __nv_bfloat16 h[4], l[4];
#pragma unroll
    for (int k = 0; k < 4; k++) {
        h[k] = __float2bfloat16(f[k]);
        l[k] = __float2bfloat16(f[k] - __bfloat162float(h[k]));
    }
    __nv_bfloat162 p0, p1, q0, q1;
    p0.x = h[0]; p0.y = h[1]; p1.x = h[2]; p1.y = h[3];
    q0.x = l[0]; q0.y = l[1]; q1.x = l[2]; q1.y = l[3];
    ((__nv_bfloat162*)hi)[i * 2] = p0; ((__nv_bfloat162*)hi)[i * 2 + 1] = p1;
    ((__nv_bfloat162*)lo)[i * 2] = q0; ((__nv_bfloat162*)lo)[i * 2 + 1] = q1;
}

// transpose W [1024 x 1024] -> Wt[n][k] hi/lo
__global__ void conv_w_t(const float* __restrict__ W0, const float* __restrict__ W1,
                         const float* __restrict__ W2, const float* __restrict__ W3,
                         const float* __restrict__ W4) {
    const float* Ws[5] = {W0, W1, W2, W3, W4};
    const float* W = Ws[blockIdx.z];
    __nv_bfloat16* hi = g_Wthi + (size_t)blockIdx.z * DIMm * DIMm;
    __nv_bfloat16* lo = g_Wtlo + (size_t)blockIdx.z * DIMm * DIMm;
    __shared__ float tile[32][33];
    int k0 = blockIdx.y * 32, n0 = blockIdx.x * 32;
    int c = threadIdx.x & 31, r8 = threadIdx.x >> 5;
#pragma unroll
    for (int i = 0; i < 4; i++) {
        int r = r8 + i * 8;
        tile[r][c] = W[(size_t)(k0 + r) * DIMm + n0 + c];
    }
    __syncthreads();
#pragma unroll
    for (int i = 0; i < 4; i++) {
        int r = r8 + i * 8;
        float v = tile[c][r];
        __nv_bfloat16 h = __float2bfloat16(v);
        hi[(size_t)(n0 + r) * DIMm + k0 + c] = h;
        lo[(size_t)(n0 + r) * DIMm + k0 + c] = __float2bfloat16(v - __bfloat162float(h));
    }
}

// ===================== HMMA GEMM (mma.sync bf16 hi/lo) =====================
// C[4096x1024] = A[4096x1024] @ Wt^T. CTA tile 128x128, warp tile 64x32.
// SMEM stage: Ahi|Alo|Bhi|Blo, each 128 rows x 32 bf16 (64B/row), swizzled.
__global__ __launch_bounds__(256)
void mma_gemm(const __nv_bfloat16* __restrict__ Ahi, const __nv_bfloat16* __restrict__ Alo,
              const __nv_bfloat16* __restrict__ WthiB, const __nv_bfloat16* __restrict__ WtloB,
              int wbase,
              float* __restrict__ C0, float* __restrict__ C1,
              float* __restrict__ C2, float* __restrict__ C3) {
    extern __shared__ __align__(1024) char smem[];
    uint32_t sbase = smem_u32(smem);
    int z = blockIdx.z;
    const __nv_bfloat16* Bh = WthiB + (size_t)(wbase + z) * DIMm * DIMm;
    const __nv_bfloat16* Bl = WtloB + (size_t)(wbase + z) * DIMm * DIMm;
    float* C = (z == 0) ? C0 : (z == 1) ? C1 : (z == 2) ? C2 : C3;

    int t = threadIdx.x;
    int lane = t & 31, w = t >> 5;
    int wm = w >> 2, wn = w & 3;
    int i0 = blockIdx.y * 128, n0 = blockIdx.x * 128;

    float acc[4][4][4] = {};

    // lane geometry
    int a_rl = ((lane >> 3) & 1) * 8 + (lane & 7);   // + wm*64 + mt*16
    int a_ch = lane >> 4;                            // k8 selector
    int b_nl = (lane & 7) + ((lane >> 4) & 1) * 8;   // + wn*32 + ng*16
    int b_ch = (lane >> 3) & 1;

    auto issue_load = [&](int ks) {
        uint32_t stage = sbase + (uint32_t)(ks & 1) * 32768u;
        int k0 = ks * 32;
#pragma unroll
        for (int i = 0; i < 8; i++) {
            int tile = i >> 1;
            int ci = ((i & 1) << 8) + t;          // 0..511
            int r = ci >> 2, c = ci & 3;
            const __nv_bfloat16* src = (tile == 0) ? Ahi : (tile == 1) ? Alo
                                     : (tile == 2) ? Bh : Bl;
            int rb = (tile < 2) ? i0 : n0;
            const __nv_bfloat16* g = src + (size_t)(rb + r) * DIMm + k0 + c * 8;
            uint32_t s = stage + (uint32_t)(tile * 8192 + r * 64 +
                          (((c ^ ((r >> 1) & 3))) << 4));
            cp_async16(s, g);
        }
        cp_commit();
    };

    issue_load(0);
    const int NS = DIMm / 32;   // 32 stages
    for (int ks = 0; ks < NS; ks++) {
        if (ks + 1 < NS) issue_load(ks + 1);
        if (ks + 1 < NS) cp_wait1(); else cp_wait0();
        __syncthreads();
        uint32_t sb = sbase + (uint32_t)(ks & 1) * 32768u;
        uint32_t aH = sb, aL = sb + 8192, bH = sb + 16384, bL = sb + 24576;
#pragma unroll
        for (int kk = 0; kk < 2; kk++) {
            int c0 = kk * 2;
            uint32_t fBh[2][4], fBl[2][4], fA[4][4];
#pragma unroll
            for (int ng = 0; ng < 2; ng++) {
                int n = wn * 32 + ng * 16 + b_nl;
                int c = c0 + b_ch;
                uint32_t off = (uint32_t)(n * 64 + ((c ^ ((n >> 1) & 3)) << 4));
                ldsm_x4(fBh[ng], bH + off);
                ldsm_x4(fBl[ng], bL + off);
            }
#pragma unroll
            for (int mt = 0; mt < 4; mt++) {
                int r = wm * 64 + mt * 16 + a_rl;
                int c = c0 + a_ch;
                uint32_t off = (uint32_t)(r * 64 + ((c ^ ((r >> 1) & 3)) << 4));
                ldsm_x4(fA[mt], aH + off);
            }
#pragma unroll
            for (int mt = 0; mt < 4; mt++)
#pragma unroll
                for (int nt = 0; nt < 4; nt++) {
                    mma16816(acc[mt][nt], fA[mt], &fBh[nt >> 1][(nt & 1) * 2]);
                    mma16816(acc[mt][nt], fA[mt], &fBl[nt >> 1][(nt & 1) * 2]);
                }
#pragma unroll
            for (int mt = 0; mt < 4; mt++) {
                int r = wm * 64 + mt * 16 + a_rl;
                int c = c0 + a_ch;
                uint32_t off = (uint32_t)(r * 64 + ((c ^ ((r >> 1) & 3)) << 4));
                ldsm_x4(fA[mt], aL + off);
            }
#pragma unroll
            for (int mt = 0; mt < 4; mt++)
#pragma unroll
                for (int nt = 0; nt < 4; nt++)
                    mma16816(acc[mt][nt], fA[mt], &fBh[nt >> 1][(nt & 1) * 2]);
        }
        __syncthreads();
    }

    int row0 = i0 + wm * 64 + (lane >> 2);
    int col0 = n0 + wn * 32 + (lane & 3) * 2;
#pragma unroll
    for (int mt = 0; mt < 4; mt++)
#pragma unroll
        for (int nt = 0; nt < 4; nt++) {
            int r = row0 + mt * 16, cc = col0 + nt * 8;
            float2 v0 = {acc[mt][nt][0], acc[mt][nt][1]};
            float2 v1 = {acc[mt][nt][2], acc[mt][nt][3]};
            *(float2*)&C[(size_t)r * DIMm + cc] = v0;
            *(float2*)&C[(size_t)(r + 8) * DIMm + cc] = v1;
        }
}

// ---------------- head-gate GEMM: C[ROWS x 16] = A @ W[1024 x 16] -----------
__global__ void gemm_hgate(const float* __restrict__ A, const float* __restrict__ W) {
    __shared__ __align__(16) float XsT[16][68];
    __shared__ float Ws[16][16];
    int t = threadIdx.x;
    int i0 = blockIdx.x * 64;
    int tx = t & 15, ty = t >> 4;
    float acc[4] = {};
    for (int k0 = 0; k0 < DIMm; k0 += 16) {
        {
            int row = t >> 2, c4 = (t & 3) * 4;
            float4 v = *(const float4*)&A[(size_t)(i0 + row) * DIMm + k0 + c4];
            XsT[c4 + 0][row] = v.x; XsT[c4 + 1][row] = v.y;
            XsT[c4 + 2][row] = v.z; XsT[c4 + 3][row] = v.w;
        }
        Ws[t >> 4][t & 15] = W[(size_t)(k0 + (t >> 4)) * Hh + (t & 15)];
        __syncthreads();
#pragma unroll
        for (int kk = 0; kk < 16; kk++) {
            float4 a = *(const float4*)&XsT[kk][ty * 4];
            float w = Ws[kk][tx];
            acc[0] += a.x * w; acc[1] += a.y * w;
            acc[2] += a.z * w; acc[3] += a.w * w;
        }
        __syncthreads();
    }
#pragma unroll
    for (int u = 0; u < 4; u++)
        g_hgraw[(size_t)(i0 + ty * 4 + u) * Hh + tx] = acc[u];
}

// ---------------- l2norm + scale + rope + layout; mem-kv prep --------------
__global__ void prep_kernel(const float* __restrict__ freqs,
                            const float* __restrict__ q_scale,
                            const float* __restrict__ k_scale,
                            const float* __restrict__ mem_k,
                            const float* __restrict__ mem_v) {
    int w = (blockIdx.x * blockDim.x + threadIdx.x) >> 5;
    int lane = threadIdx.x & 31;
    const int MAIN = Bb * Nn * Hh;
    if (w < MAIN) {
        int b = w / (Nn * Hh); int r = w % (Nn * Hh);
        int n = r / Hh; int h = r % Hh;
        size_t src = (size_t)(b * Nn + n) * DIMm + h * DHh;
        float2 q2 = ((const float2*)&g_Qraw[src])[lane];
        float2 k2 = ((const float2*)&g_Kraw[src])[lane];
        float2 v2 = ((const float2*)&g_Vraw[src])[lane];
        float ssq = q2.x * q2.x + q2.y * q2.y;
        float ssk = k2.x * k2.x + k2.y * k2.y;
        for (int o = 16; o > 0; o >>= 1) {
            ssq += __shfl_xor_sync(~0u, ssq, o);
            ssk += __shfl_xor_sync(~0u, ssk, o);
        }
        float invq = 1.0f / fmaxf(sqrtf(ssq), 1e-12f);
        float invk = 1.0f / fmaxf(sqrtf(ssk), 1e-12f);
        float sqx = q_scale[h * DHh + 2 * lane], sqy = q_scale[h * DHh + 2 * lane + 1];
        float skx = k_scale[h * DHh + 2 * lane], sky = k_scale[h * DHh + 2 * lane + 1];
        float qx = q2.x * invq * sqx, qy = q2.y * invq * sqy;
        float kx = k2.x * invk * skx, ky = k2.y * invk * sky;
        float f = freqs[n * DHh + 2 * lane];
        float cf = cosf(f), sf = sinf(f);
        float2 qo = {qx * cf - qy * sf, qy * cf + qx * sf};
        float2 ko = {kx * cf - ky * sf, ky * cf + kx * sf};
        ((float2*)&g_Qp[((size_t)(b * Hh + h) * Nn + n) * DHh])[lane] = qo;
        ((float2*)&g_Kp[((size_t)(b * Hh + h) * NJ + Mm + n) * DHh])[lane] = ko;
        ((float2*)&g_Vp[((size_t)(b * Hh + h) * NJ + Mm + n) * DHh])[lane] = v2;
    } else {
        int w2 = w - MAIN;
        if (w2 < Bb * Hh * Mm) {
            int b = w2 / (Hh * Mm); int r = w2 % (Hh * Mm);
            int h = r / Mm; int m = r % Mm;
            float2 mk = ((const float2*)&mem_k[(size_t)(h * Mm + m) * DHh])[lane];
            float2 mv = ((const float2*)&mem_v[(size_t)(h * Mm + m) * DHh])[lane];
            float ss = mk.x * mk.x + mk.y * mk.y;
            for (int o = 16; o > 0; o >>= 1) ss += __shfl_xor_sync(~0u, ss, o);
            float inv = 1.0f / fmaxf(sqrtf(ss), 1e-12f);
            float2 ko = {mk.x * inv * k_scale[h * DHh + 2 * lane],
                         mk.y * inv * k_scale[h * DHh + 2 * lane + 1]};
            ((float2*)&g_Kp[((size_t)(b * Hh + h) * NJ + m) * DHh])[lane] = ko;
            ((float2*)&g_Vp[((size_t)(b * Hh + h) * NJ + m) * DHh])[lane] = mv;
        }
    }
}

// ---------------- dots[b,h] = Qp[b,h] @ Kp[b,h]^T * QK_SCALE ---------------
__global__ void dots_kernel() {
    int bh = blockIdx.z;
    int i0 = blockIdx.y * 64;
    int j0 = blockIdx.x * 64;
    if (j0 >= i0 + 80) return;
    __shared__ __align__(16) float QsT[64][68];
    __shared__ __align__(16) float KsT[64][68];
    int t = threadIdx.x;
    const float* Q = &g_Qp[(size_t)bh * Nn * DHh];
    const float* Kk = &g_Kp[(size_t)bh * NJ * DHh];
#pragma unroll
    for (int s = 0; s < 4; s++) {
        int f = t + s * 256;
        int row = f >> 4, c4 = (f & 15) * 4;
        float4 v = *(const float4*)&Q[(size_t)(i0 + row) * DHh + c4];
        QsT[c4 + 0][row] = v.x; QsT[c4 + 1][row] = v.y;
        QsT[c4 + 2][row] = v.z; QsT[c4 + 3][row] = v.w;
    }
#pragma unroll
    for (int s = 0; s < 4; s++) {
        int f = t + s * 256;
        int row = f >> 4, c4 = (f & 15) * 4;
        float4 v = make_float4(0.f, 0.f, 0.f, 0.f);
        if (j0 + row < NJ) v = *(const float4*)&Kk[(size_t)(j0 + row) * DHh + c4];
        KsT[c4 + 0][row] = v.x; KsT[c4 + 1][row] = v.y;
        KsT[c4 + 2][row] = v.z; KsT[c4 + 3][row] = v.w;
    }
    __syncthreads();
    int tx = t & 15, ty = t >> 4;
    float acc[4][4] = {};
#pragma unroll 8
    for (int d = 0; d < 64; d++) {
        float4 a = *(const float4*)&QsT[d][ty * 4];
        float4 b = *(const float4*)&KsT[d][tx * 4];
        float av[4] = {a.x, a.y, a.z, a.w};
        float bv[4] = {b.x, b.y, b.z, b.w};
#pragma unroll
        for (int u = 0; u < 4; u++)
#pragma unroll
            for (int v2 = 0; v2 < 4; v2++) acc[u][v2] += av[u] * bv[v2];
    }
    if (j0 + tx * 4 < NJ) {
#pragma unroll
        for (int u = 0; u < 4; u++) {
            float4 o = {acc[u][0] * QK_SCALE, acc[u][1] * QK_SCALE,
                        acc[u][2] * QK_SCALE, acc[u][3] * QK_SCALE};
            *(float4*)&g_dots[((size_t)bh * Nn + i0 + ty * 4 + u) * NJ + j0 + tx * 4] = o;
        }
    }
}

// ------- fused: pre-mix (W_pre) -> per-head softmax -> post-mix (W_post) ----
__global__ void softmax_kernel(const float* __restrict__ W_pre,
                               const float* __restrict__ W_post) {
    extern __shared__ float smemf[];
    float* sD = smemf;
    float* sT = sD + 16 * NJ;
    float* sWpre = sT + 16 * 64;
    float* sWpost = sWpre + 256;
    int t = threadIdx.x;
    int i = blockIdx.x, b = blockIdx.y;
    sWpre[t] = W_pre[t];
    sWpost[t] = W_post[t];
    int jcount = i + 17;
    __syncthreads();
    int g = t >> 4, q = t & 15;
    for (int j0 = 0; j0 < jcount; j0 += 64) {
        for (int idx = t; idx < 1024; idx += 256) {
            int h = idx >> 6, jj = idx & 63, j = j0 + jj;
            sT[idx] = (j < jcount)
                ? g_dots[((size_t)(b * Hh + h) * Nn + i) * NJ + j] : 0.f;
        }
        __syncthreads();
#pragma unroll
        for (int u = 0; u < 4; u++) {
            int jj = q * 4 + u, j = j0 + jj;
            if (j < jcount) {
                float a = 0.f;
#pragma unroll
                for (int h = 0; h < 16; h++) a += sWpre[g * 16 + h] * sT[h * 64 + jj];
                sD[g * NJ + j] = a;
            }
        }
        __syncthreads();
    }
    int warp = t >> 5, lane = t & 31;
    for (int gg = warp; gg < 16; gg += 8) {
        float* row = sD + gg * NJ;
        float m = -FLT_MAX;
        for (int j = lane; j < jcount; j += 32) m = fmaxf(m, row[j]);
        for (int o = 16; o > 0; o >>= 1) m = fmaxf(m, __shfl_xor_sync(~0u, m, o));
        float l = 0.f;
        for (int j = lane; j < jcount; j += 32) {
            float e = expf(row[j] - m); row[j] = e; l += e;
        }
        for (int o = 16; o > 0; o >>= 1) l += __shfl_xor_sync(~0u, l, o);
        float inv = 1.f / l;
        for (int j = lane; j < jcount; j += 32) row[j] *= inv;
    }
    __syncthreads();
    int i0 = i & ~63;
    int jend = min(NJ, i0 + 128);
    for (int j0 = 0; j0 < jend; j0 += 64) {
        float vals[4];
#pragma unroll
        for (int u = 0; u < 4; u++) {
            int j = j0 + q * 4 + u;
            float a = 0.f;
            if (j < jcount) {
#pragma unroll
                for (int h = 0; h < 16; h++) a += sWpost[g * 16 + h] * sD[h * NJ + j];
            }
            vals[u] = a;
        }
        int j = j0 + q * 4;
        if (j < jend) {
            float4 o = {vals[0], vals[1], vals[2], vals[3]};
            *(float4*)&g_dots[((size_t)(b * Hh + g) * Nn + i) * NJ + j] = o;
        }
    }
}

// ------- out[b,g] = attn2[b,g] @ Vp[b,g], fused head+value gates -----------
__global__ void av_kernel(const float* __restrict__ b_hgate,
                          const float* __restrict__ b_vgate) {
    int bg = blockIdx.y;
    int i0 = blockIdx.x * 64;
    int jlimit = min(NJ, i0 + 128);
    __shared__ __align__(16) float AsT[64][68];
    __shared__ __align__(16) float Vs[64][68];
    int t = threadIdx.x, tx = t & 15, ty = t >> 4;
    float acc[4][4] = {};
    const float* attn = &g_dots[(size_t)bg * Nn * NJ];
    const float* V = &g_Vp[(size_t)bg * NJ * DHh];
    for (int j0 = 0; j0 < jlimit; j0 += 64) {
#pragma unroll
        for (int s = 0; s < 4; s++) {
            int f = t + s * 256;
            int row = f >> 4, c4 = (f & 15) * 4;
            float4 v = make_float4(0.f, 0.f, 0.f, 0.f);
            if (j0 + c4 < NJ) v = *(const float4*)&attn[(size_t)(i0 + row) * NJ + j0 + c4];
            AsT[c4 + 0][row] = v.x; AsT[c4 + 1][row] = v.y;
            AsT[c4 + 2][row] = v.z; AsT[c4 + 3][row] = v.w;
        }
#pragma unroll
        for (int s = 0; s < 4; s++) {
            int f = t + s * 256;
            int jr = f >> 4, c4 = (f & 15) * 4;
            float4 v = make_float4(0.f, 0.f, 0.f, 0.f);
            if (j0 + jr < NJ) v = *(const float4*)&V[(size_t)(j0 + jr) * DHh + c4];
            *(float4*)&Vs[jr][c4] = v;
        }
        __syncthreads();
#pragma unroll 8
        for (int jj = 0; jj < 64; jj++) {
            float4 a = *(const float4*)&AsT[jj][ty * 4];
            float4 bb = *(const float4*)&Vs[jj][tx * 4];
            float av[4] = {a.x, a.y, a.z, a.w};
            float bv[4] = {bb.x, bb.y, bb.z, bb.w};
#pragma unroll
            for (int u = 0; u < 4; u++)
#pragma unroll
                for (int v2 = 0; v2 < 4; v2++) acc[u][v2] += av[u] * bv[v2];
        }
        __syncthreads();
    }
    int b = bg >> 4, g = bg & 15;
#pragma unroll
    for (int u = 0; u < 4; u++) {
        int i = i0 + ty * 4 + u;
        size_t rbase = (size_t)(b * Nn + i);
        float hg = 1.f / (1.f + expf(-(g_hgraw[rbase * Hh + g] + b_hgate[g])));
#pragma unroll
        for (int v2 = 0; v2 < 4; v2++) {
            int d = tx * 4 + v2;
            float vgv = 1.f / (1.f + expf(-(g_vgraw[rbase * DIMm + g * DHh + d] +
                                            b_vgate[g * DHh + d])));
            g_outg[rbase * DIMm + g * DHh + d] = acc[u][v2] * hg * vgv;
        }
    }
}

// ---------------------------------------------------------------------------
extern "C" void kernel_launch(void* const* d_in, const int* in_sizes, int n_in,
                              void* d_out, int out_size) {
    const float* x       = (const float*)d_in[0];
    const float* freqs   = (const float*)d_in[1];
    const float* Wq      = (const float*)d_in[2];
    const float* Wk      = (const float*)d_in[3];
    const float* Wv      = (const float*)d_in[4];
    const float* q_scale = (const float*)d_in[5];
    const float* k_scale = (const float*)d_in[6];
    const float* mem_k   = (const float*)d_in[7];
    const float* mem_v   = (const float*)d_in[8];
    const float* W_pre   = (const float*)d_in[9];
    const float* W_post  = (const float*)d_in[10];
    const float* W_hgate = (const float*)d_in[11];
    const float* b_hgate = (const float*)d_in[12];
    const float* W_vgate = (const float*)d_in[13];
    const float* b_vgate = (const float*)d_in[14];
    const float* Wo      = (const float*)d_in[15];
    float* out = (float*)d_out;

    float *Qraw, *Kraw, *Vraw, *vgraw, *outg;
    __nv_bfloat16 *Ahi, *Alo, *Wthi, *Wtlo;
    cudaGetSymbolAddress((void**)&Qraw, g_Qraw);
    cudaGetSymbolAddress((void**)&Kraw, g_Kraw);
    cudaGetSymbolAddress((void**)&Vraw, g_Vraw);
    cudaGetSymbolAddress((void**)&vgraw, g_vgraw);
    cudaGetSymbolAddress((void**)&outg, g_outg);
    cudaGetSymbolAddress((void**)&Ahi, g_Ahi);
    cudaGetSymbolAddress((void**)&Alo, g_Alo);
    cudaGetSymbolAddress((void**)&Wthi, g_Wthi);
    cudaGetSymbolAddress((void**)&Wtlo, g_Wtlo);

    conv_hilo<<<ROWS * DIMm / 1024, 256>>>(x, Ahi, Alo);
    conv_w_t<<<dim3(32, 32, 5), 256>>>(Wq, Wk, Wv, W_vgate, Wo);

    cudaFuncSetAttribute(mma_gemm, cudaFuncAttributeMaxDynamicSharedMemorySize, 65536);
    // 4 projection GEMMs in one launch (z selects the weight & output)
    mma_gemm<<<dim3(DIMm / 128, ROWS / 128, 4), 256, 65536>>>(
        Ahi, Alo, Wthi, Wtlo, 0, Qraw, Kraw, Vraw, vgraw);
    gemm_hgate<<<ROWS / 64, 256>>>(x, W_hgate);

    int warps = Bb * Nn * Hh + Bb * Hh * Mm;
    prep_kernel<<<(warps + 7) / 8, 256>>>(freqs, q_scale, k_scale, mem_k, mem_v);

    dots_kernel<<<dim3((NJ + 63) / 64, Nn / 64, Bb * Hh), 256>>>();

    size_t smem_bytes = (16 * NJ + 16 * 64 + 512) * sizeof(float);
    cudaFuncSetAttribute(softmax_kernel, cudaFuncAttributeMaxDynamicSharedMemorySize,
                         (int)smem_bytes);
    softmax_kernel<<<dim3(Nn, Bb), 256, smem_bytes>>>(W_pre, W_post);

    av_kernel<<<dim3(Nn / 64, Bb * Hh), 256>>>(b_hgate, b_vgate);

    conv_hilo<<<ROWS * DIMm / 1024, 256>>>(outg, Ahi, Alo);
    mma_gemm<<<dim3(DIMm / 128, ROWS / 128, 1), 256, 65536>>>(
        Ahi, Alo, Wthi, Wtlo, 4, out, out, out, out);
}

// round 5
// speedup vs baseline: 3.6869x; 1.3998x over previous
#include <cuda_runtime.h>
#include <cuda_bf16.h>
#include <math.h>
#include <float.h>
#include <stdint.h>

#define Bb   4
#define Nn   1024
#define DIMm 1024
#define Hh   16
#define DHh  64
#define Mm   16
#define NJ   1040          // M + N
#define PJ   1088          // padded kv length (multiple of 64)
#define ROWS 4096          // B*N
#define QK_SCALE 10.0f

// ===================== scratch =============================================
__device__ float g_Qraw[(size_t)ROWS * DIMm];
__device__ float g_Kraw[(size_t)ROWS * DIMm];
__device__ float g_Vraw[(size_t)ROWS * DIMm];
__device__ float g_vgraw[(size_t)ROWS * DIMm];
__device__ float g_hgraw[(size_t)ROWS * Hh];
__device__ float g_dots[(size_t)64 * Nn * NJ];
__device__ float g_Ohd[(size_t)64 * Nn * DHh];
__device__ float g_Whgt[16 * 1024];
__device__ __nv_bfloat16 g_Qh[(size_t)64 * Nn * DHh];
__device__ __nv_bfloat16 g_Ql[(size_t)64 * Nn * DHh];
__device__ __nv_bfloat16 g_Kh[(size_t)64 * PJ * DHh];   // pad rows stay zero
__device__ __nv_bfloat16 g_Kl[(size_t)64 * PJ * DHh];
__device__ __nv_bfloat16 g_Vh[(size_t)64 * PJ * DHh];
__device__ __nv_bfloat16 g_Vl[(size_t)64 * PJ * DHh];
__device__ __nv_bfloat16 g_Phi[(size_t)64 * Nn * PJ];
__device__ __nv_bfloat16 g_Plo[(size_t)64 * Nn * PJ];
__device__ __nv_bfloat16 g_Ahi[(size_t)ROWS * DIMm];
__device__ __nv_bfloat16 g_Alo[(size_t)ROWS * DIMm];
__device__ __nv_bfloat16 g_Wthi[(size_t)5 * DIMm * DIMm];
__device__ __nv_bfloat16 g_Wtlo[(size_t)5 * DIMm * DIMm];

// ===================== PTX helpers (base ISA only) =========================
__device__ __forceinline__ uint32_t smem_u32(const void* p) {
    uint32_t a;
    asm("{ .reg .u64 tmp; cvta.to.shared.u64 tmp, %1; cvt.u32.u64 %0, tmp; }"
        : "=r"(a) : "l"(p));
    return a;
}
__device__ __forceinline__ void cp_async16(uint32_t s, const void* g) {
    asm volatile("cp.async.cg.shared.global [%0], [%1], 16;" :: "r"(s), "l"(g));
}
__device__ __forceinline__ void cp_commit() {
    asm volatile("cp.async.commit_group;" ::: "memory");
}
__device__ __forceinline__ void cp_wait1() {
    asm volatile("cp.async.wait_group 1;" ::: "memory");
}
__device__ __forceinline__ void cp_wait0() {
    asm volatile("cp.async.wait_group 0;" ::: "memory");
}
__device__ __forceinline__ void ldsm_x4(uint32_t* r, uint32_t addr) {
    asm volatile("ldmatrix.sync.aligned.m8n8.x4.shared.b16 {%0,%1,%2,%3}, [%4];"
                 : "=r"(r[0]), "=r"(r[1]), "=r"(r[2]), "=r"(r[3]) : "r"(addr));
}
__device__ __forceinline__ void ldsm_x4_t(uint32_t* r, uint32_t addr) {
    asm volatile("ldmatrix.sync.aligned.m8n8.x4.trans.shared.b16 {%0,%1,%2,%3}, [%4];"
                 : "=r"(r[0]), "=r"(r[1]), "=r"(r[2]), "=r"(r[3]) : "r"(addr));
}
__device__ __forceinline__ void mma16816(float* d, const uint32_t* a, const uint32_t* b) {
    asm volatile(
        "mma.sync.aligned.m16n8k16.row.col.f32.bf16.bf16.f32 "
        "{%0,%1,%2,%3}, {%4,%5,%6,%7}, {%8,%9}, {%0,%1,%2,%3};"
        : "+f"(d[0]), "+f"(d[1]), "+f"(d[2]), "+f"(d[3])
        : "r"(a[0]), "r"(a[1]), "r"(a[2]), "r"(a[3]), "r"(b[0]), "r"(b[1]));
}

// ===================== convert kernels =====================================
__global__ void conv_hilo(const float* __restrict__ src,
                          __nv_bfloat16* __restrict__ hi,
                          __nv_bfloat16* __restrict__ lo) {
    int i = blockIdx.x * 256 + threadIdx.x;
    float4 v = ((const float4*)src)[i];
    float f[4] = {v.x, v.y, v.z, v.w};
    __nv_bfloat16 h[4], l[4];
#pragma unroll
    for (int k = 0; k < 4; k++) {
        h[k] = __float2bfloat16(f[k]);
        l[k] = __float2bfloat16(f[k] - __bfloat162float(h[k]));
    }
    __nv_bfloat162 p0, p1, q0, q1;
    p0.x = h[0]; p0.y = h[1]; p1.x = h[2]; p1.y = h[3];
    q0.x = l[0]; q0.y = l[1]; q1.x = l[2]; q1.y = l[3];
    ((__nv_bfloat162*)hi)[i * 2] = p0; ((__nv_bfloat162*)hi)[i * 2 + 1] = p1;
    ((__nv_bfloat162*)lo)[i * 2] = q0; ((__nv_bfloat162*)lo)[i * 2 + 1] = q1;
}

__global__ void conv_w_t(const float* __restrict__ W0, const float* __restrict__ W1,
                         const float* __restrict__ W2, const float* __restrict__ W3,
                         const float* __restrict__ W4) {
    const float* Ws[5] = {W0, W1, W2, W3, W4};
    const float* W = Ws[blockIdx.z];
    __nv_bfloat16* hi = g_Wthi + (size_t)blockIdx.z * DIMm * DIMm;
    __nv_bfloat16* lo = g_Wtlo + (size_t)blockIdx.z * DIMm * DIMm;
    __shared__ float tile[32][33];
    int k0 = blockIdx.y * 32, n0 = blockIdx.x * 32;
    int c = threadIdx.x & 31, r8 = threadIdx.x >> 5;
#pragma unroll
    for (int i = 0; i < 4; i++) {
        int r = r8 + i * 8;
        tile[r][c] = W[(size_t)(k0 + r) * DIMm + n0 + c];
    }
    __syncthreads();
#pragma unroll
    for (int i = 0; i < 4; i++) {
        int r = r8 + i * 8;
        float v = tile[c][r];
        __nv_bfloat16 h = __float2bfloat16(v);
        hi[(size_t)(n0 + r) * DIMm + k0 + c] = h;
        lo[(size_t)(n0 + r) * DIMm + k0 + c] = __float2bfloat16(v - __bfloat162float(h));
    }
}

__global__ void hg_t(const float* __restrict__ W) {
    int idx = blockIdx.x * 256 + threadIdx.x;   // 16384
    int h = idx >> 10, k = idx & 1023;
    g_Whgt[idx] = W[k * 16 + h];
}

// ===================== HMMA projection/output GEMM =========================
__global__ __launch_bounds__(256)
void mma_gemm(const __nv_bfloat16* __restrict__ Ahi, const __nv_bfloat16* __restrict__ Alo,
              const __nv_bfloat16* __restrict__ WthiB, const __nv_bfloat16* __restrict__ WtloB,
              int wbase,
              float* __restrict__ C0, float* __restrict__ C1,
              float* __restrict__ C2, float* __restrict__ C3) {
    extern __shared__ __align__(1024) char smem[];
    uint32_t sbase = smem_u32(smem);
    int z = blockIdx.z;
    const __nv_bfloat16* Bh = WthiB + (size_t)(wbase + z) * DIMm * DIMm;
    const __nv_bfloat16* Bl = WtloB + (size_t)(wbase + z) * DIMm * DIMm;
    float* C = (z == 0) ? C0 : (z == 1) ? C1 : (z == 2) ? C2 : C3;

    int t = threadIdx.x;
    int lane = t & 31, w = t >> 5;
    int wm = w >> 2, wn = w & 3;
    int i0 = blockIdx.y * 128, n0 = blockIdx.x * 128;

    float acc[4][4][4] = {};

    int a_rl = ((lane >> 3) & 1) * 8 + (lane & 7);
    int a_ch = lane >> 4;
    int b_nl = (lane & 7) + ((lane >> 4) & 1) * 8;
    int b_ch = (lane >> 3) & 1;

    auto issue_load = [&](int ks) {
        uint32_t stage = sbase + (uint32_t)(ks & 1) * 32768u;
        int k0 = ks * 32;
#pragma unroll
        for (int i = 0; i < 8; i++) {
            int tile = i >> 1;
            int ci = ((i & 1) << 8) + t;
            int r = ci >> 2, c = ci & 3;
            const __nv_bfloat16* src = (tile == 0) ? Ahi : (tile == 1) ? Alo
                                     : (tile == 2) ? Bh : Bl;
            int rb = (tile < 2) ? i0 : n0;
            const __nv_bfloat16* g = src + (size_t)(rb + r) * DIMm + k0 + c * 8;
            uint32_t s = stage + (uint32_t)(tile * 8192 + r * 64 +
                          (((c ^ ((r >> 1) & 3))) << 4));
            cp_async16(s, g);
        }
        cp_commit();
    };

    issue_load(0);
    const int NS = DIMm / 32;
    for (int ks = 0; ks < NS; ks++) {
        if (ks + 1 < NS) issue_load(ks + 1);
        if (ks + 1 < NS) cp_wait1(); else cp_wait0();
        __syncthreads();
        uint32_t sb = sbase + (uint32_t)(ks & 1) * 32768u;
        uint32_t aH = sb, aL = sb + 8192, bH = sb + 16384, bL = sb + 24576;
#pragma unroll
        for (int kk = 0; kk < 2; kk++) {
            int c0 = kk * 2;
            uint32_t fBh[2][4], fBl[2][4], fA[4][4];
#pragma unroll
            for (int ng = 0; ng < 2; ng++) {
                int n = wn * 32 + ng * 16 + b_nl;
                int c = c0 + b_ch;
                uint32_t off = (uint32_t)(n * 64 + ((c ^ ((n >> 1) & 3)) << 4));
                ldsm_x4(fBh[ng], bH + off);
                ldsm_x4(fBl[ng], bL + off);
            }
#pragma unroll
            for (int mt = 0; mt < 4; mt++) {
                int r = wm * 64 + mt * 16 + a_rl;
                int c = c0 + a_ch;
                uint32_t off = (uint32_t)(r * 64 + ((c ^ ((r >> 1) & 3)) << 4));
                ldsm_x4(fA[mt], aH + off);
            }
#pragma unroll
            for (int mt = 0; mt < 4; mt++)
#pragma unroll
                for (int nt = 0; nt < 4; nt++) {
                    mma16816(acc[mt][nt], fA[mt], &fBh[nt >> 1][(nt & 1) * 2]);
                    mma16816(acc[mt][nt], fA[mt], &fBl[nt >> 1][(nt & 1) * 2]);
                }
#pragma unroll
            for (int mt = 0; mt < 4; mt++) {
                int r = wm * 64 + mt * 16 + a_rl;
                int c = c0 + a_ch;
                uint32_t off = (uint32_t)(r * 64 + ((c ^ ((r >> 1) & 3)) << 4));
                ldsm_x4(fA[mt], aL + off);
            }
#pragma unroll
            for (int mt = 0; mt < 4; mt++)
#pragma unroll
                for (int nt = 0; nt < 4; nt++)
                    mma16816(acc[mt][nt], fA[mt], &fBh[nt >> 1][(nt & 1) * 2]);
        }
        __syncthreads();
    }

    int row0 = i0 + wm * 64 + (lane >> 2);
    int col0 = n0 + wn * 32 + (lane & 3) * 2;
#pragma unroll
    for (int mt = 0; mt < 4; mt++)
#pragma unroll
        for (int nt = 0; nt < 4; nt++) {
            int r = row0 + mt * 16, cc = col0 + nt * 8;
            float2 v0 = {acc[mt][nt][0], acc[mt][nt][1]};
            float2 v1 = {acc[mt][nt][2], acc[mt][nt][3]};
            *(float2*)&C[(size_t)r * DIMm + cc] = v0;
            *(float2*)&C[(size_t)(r + 8) * DIMm + cc] = v1;
        }
}

// ---------------- head-gate: warp per row ----------------------------------
__global__ __launch_bounds__(128) void hgate_warp(const float* __restrict__ x) {
    int w = blockIdx.x * 4 + (threadIdx.x >> 5);
    int l = threadIdx.x & 31;
    float acc[16] = {};
    const float* xr = x + (size_t)w * 1024;
#pragma unroll
    for (int i = 0; i < 8; i++) {
        float4 xv = *(const float4*)&xr[i * 128 + l * 4];
#pragma unroll
        for (int h = 0; h < 16; h++) {
            float4 wv = *(const float4*)&g_Whgt[h * 1024 + i * 128 + l * 4];
            acc[h] += xv.x * wv.x + xv.y * wv.y + xv.z * wv.z + xv.w * wv.w;
        }
    }
#pragma unroll
    for (int h = 0; h < 16; h++)
#pragma unroll
        for (int o = 16; o > 0; o >>= 1) acc[h] += __shfl_xor_sync(~0u, acc[h], o);
    if (l == 0) {
#pragma unroll
        for (int h = 0; h < 16; h++) g_hgraw[(size_t)w * 16 + h] = acc[h];
    }
}

// ---------------- l2norm + scale + rope -> bf16 hi/lo ----------------------
__device__ __forceinline__ void wr_hl(__nv_bfloat16* H, __nv_bfloat16* L,
                                      size_t rowoff, int lane, float2 v) {
    __nv_bfloat16 hx = __float2bfloat16(v.x), hy = __float2bfloat16(v.y);
    __nv_bfloat162 hh; hh.x = hx; hh.y = hy;
    __nv_bfloat162 ll;
    ll.x = __float2bfloat16(v.x - __bfloat162float(hx));
    ll.y = __float2bfloat16(v.y - __bfloat162float(hy));
    ((__nv_bfloat162*)(H + rowoff))[lane] = hh;
    ((__nv_bfloat162*)(L + rowoff))[lane] = ll;
}

__global__ void prep_kernel(const float* __restrict__ freqs,
                            const float* __restrict__ q_scale,
                            const float* __restrict__ k_scale,
                            const float* __restrict__ mem_k,
                            const float* __restrict__ mem_v) {
    int w = (blockIdx.x * blockDim.x + threadIdx.x) >> 5;
    int lane = threadIdx.x & 31;
    const int MAIN = Bb * Nn * Hh;
    if (w < MAIN) {
        int b = w / (Nn * Hh); int r = w % (Nn * Hh);
        int n = r / Hh; int h = r % Hh;
        size_t src = (size_t)(b * Nn + n) * DIMm + h * DHh;
        float2 q2 = ((const float2*)&g_Qraw[src])[lane];
        float2 k2 = ((const float2*)&g_Kraw[src])[lane];
        float2 v2 = ((const float2*)&g_Vraw[src])[lane];
        float ssq = q2.x * q2.x + q2.y * q2.y;
        float ssk = k2.x * k2.x + k2.y * k2.y;
        for (int o = 16; o > 0; o >>= 1) {
            ssq += __shfl_xor_sync(~0u, ssq, o);
            ssk += __shfl_xor_sync(~0u, ssk, o);
        }
        float invq = 1.0f / fmaxf(sqrtf(ssq), 1e-12f);
        float invk = 1.0f / fmaxf(sqrtf(ssk), 1e-12f);
        float sqx = q_scale[h * DHh + 2 * lane], sqy = q_scale[h * DHh + 2 * lane + 1];
        float skx = k_scale[h * DHh + 2 * lane], sky = k_scale[h * DHh + 2 * lane + 1];
        float qx = q2.x * invq * sqx, qy = q2.y * invq * sqy;
        float kx = k2.x * invk * skx, ky = k2.y * invk * sky;
        float f = freqs[n * DHh + 2 * lane];
        float cf = cosf(f), sf = sinf(f);
        float2 qo = {qx * cf - qy * sf, qy * cf + qx * sf};
        float2 ko = {kx * cf - ky * sf, ky * cf + kx * sf};
        int bh = b * Hh + h;
        wr_hl(g_Qh, g_Ql, ((size_t)bh * Nn + n) * DHh, lane, qo);
        wr_hl(g_Kh, g_Kl, ((size_t)bh * PJ + Mm + n) * DHh, lane, ko);
        wr_hl(g_Vh, g_Vl, ((size_t)bh * PJ + Mm + n) * DHh, lane, v2);
    } else {
        int w2 = w - MAIN;
        if (w2 < Bb * Hh * Mm) {
            int b = w2 / (Hh * Mm); int r = w2 % (Hh * Mm);
            int h = r / Mm; int m = r % Mm;
            float2 mk = ((const float2*)&mem_k[(size_t)(h * Mm + m) * DHh])[lane];
            float2 mv = ((const float2*)&mem_v[(size_t)(h * Mm + m) * DHh])[lane];
            float ss = mk.x * mk.x + mk.y * mk.y;
            for (int o = 16; o > 0; o >>= 1) ss += __shfl_xor_sync(~0u, ss, o);
            float inv = 1.0f / fmaxf(sqrtf(ss), 1e-12f);
            float2 ko = {mk.x * inv * k_scale[h * DHh + 2 * lane],
                         mk.y * inv * k_scale[h * DHh + 2 * lane + 1]};
            int bh = b * Hh + h;
            wr_hl(g_Kh, g_Kl, ((size_t)bh * PJ + m) * DHh, lane, ko);
            wr_hl(g_Vh, g_Vl, ((size_t)bh * PJ + m) * DHh, lane, mv);
        }
    }
}

// ---------------- dots = Q K^T (HMMA bf16 hi/lo, raw scores) ---------------
__global__ __launch_bounds__(128) void dots_hmma() {
    int bh = blockIdx.z;
    int i0 = blockIdx.y * 64, j0 = blockIdx.x * 64;
    if (j0 >= i0 + 80) return;
    __shared__ __align__(128) char sm[32768];
    uint32_t sb = smem_u32(sm);
    int t = threadIdx.x, lane = t & 31, w = t >> 5;
    const __nv_bfloat16* Qh = g_Qh + ((size_t)bh * Nn + i0) * DHh;
    const __nv_bfloat16* Ql = g_Ql + ((size_t)bh * Nn + i0) * DHh;
    const __nv_bfloat16* Kh = g_Kh + ((size_t)bh * PJ + j0) * DHh;
    const __nv_bfloat16* Kl = g_Kl + ((size_t)bh * PJ + j0) * DHh;
#pragma unroll
    for (int i = 0; i < 16; i++) {
        int idx = t + i * 128;
        int tile = idx >> 9;
        int ci = idx & 511, r = ci >> 3, c = ci & 7;
        const __nv_bfloat16* src = (tile == 0) ? Qh : (tile == 1) ? Ql
                                 : (tile == 2) ? Kh : Kl;
        cp_async16(sb + tile * 8192 + r * 128 + ((c ^ (r & 7)) << 4),
                   src + (size_t)r * DHh + c * 8);
    }
    cp_commit(); cp_wait0();
    __syncthreads();
    int m0 = w * 16;
    float acc[8][4] = {};
    int a_r = m0 + ((lane >> 3) & 1) * 8 + (lane & 7);
    int a_c2 = lane >> 4;
    int b_r = (lane & 7) + ((lane >> 4) & 1) * 8;
    int b_c2 = (lane >> 3) & 1;
    uint32_t aH = sb, aL = sb + 8192, bH = sb + 16384, bL = sb + 24576;
#pragma unroll
    for (int pass = 0; pass < 3; pass++) {
        uint32_t at = (pass == 2) ? aL : aH;
        uint32_t bt = (pass == 1) ? bL : bH;
#pragma unroll
        for (int kk = 0; kk < 4; kk++) {
            uint32_t fA[4];
            int c = kk * 2 + a_c2;
            ldsm_x4(fA, at + a_r * 128 + ((c ^ (a_r & 7)) << 4));
#pragma unroll
            for (int ng = 0; ng < 4; ng++) {
                uint32_t fB[4];
                int n = ng * 16 + b_r;
                int cb = kk * 2 + b_c2;
                ldsm_x4(fB, bt + n * 128 + ((cb ^ (n & 7)) << 4));
                mma16816(acc[ng * 2], fA, fB);
                mma16816(acc[ng * 2 + 1], fA, fB + 2);
            }
        }
    }
    int row = i0 + m0 + (lane >> 2);
    int cb = (lane & 3) * 2;
    float* D = g_dots + (size_t)bh * Nn * NJ;
#pragma unroll
    for (int nb = 0; nb < 8; nb++) {
        int col = j0 + nb * 8 + cb;
        if (col < NJ) {
            float2 v0 = {acc[nb][0], acc[nb][1]};
            float2 v1 = {acc[nb][2], acc[nb][3]};
            *(float2*)&D[(size_t)row * NJ + col] = v0;
            *(float2*)&D[(size_t)(row + 8) * NJ + col] = v1;
        }
    }
}

// --- fused: pre-mix (W_pre*QK_SCALE) -> softmax -> post-mix -> bf16 hi/lo --
__global__ void softmax_kernel(const float* __restrict__ W_pre,
                               const float* __restrict__ W_post) {
    extern __shared__ float smemf[];
    float* sD = smemf;                 // 16 * NJ
    float* sT = sD + 16 * NJ;          // 16 * 64
    float* sWpre = sT + 16 * 64;       // 256
    float* sWpost = sWpre + 256;       // 256
    int t = threadIdx.x;
    int i = blockIdx.x, b = blockIdx.y;
    sWpre[t] = W_pre[t] * QK_SCALE;
    sWpost[t] = W_post[t];
    int jcount = i + 17;
    __syncthreads();
    int g = t >> 4, q = t & 15;
    for (int j0 = 0; j0 < jcount; j0 += 64) {
        for (int idx = t; idx < 1024; idx += 256) {
            int h = idx >> 6, jj = idx & 63, j = j0 + jj;
            sT[idx] = (j < jcount)
                ? g_dots[((size_t)(b * Hh + h) * Nn + i) * NJ + j] : 0.f;
        }
        __syncthreads();
#pragma unroll
        for (int u = 0; u < 4; u++) {
            int jj = q * 4 + u, j = j0 + jj;
            if (j < jcount) {
                float a = 0.f;
#pragma unroll
                for (int h = 0; h < 16; h++) a += sWpre[g * 16 + h] * sT[h * 64 + jj];
                sD[g * NJ + j] = a;
            }
        }
        __syncthreads();
    }
    int warp = t >> 5, lane = t & 31;
    for (int gg = warp; gg < 16; gg += 8) {
        float* row = sD + gg * NJ;
        float m = -FLT_MAX;
        for (int j = lane; j < jcount; j += 32) m = fmaxf(m, row[j]);
        for (int o = 16; o > 0; o >>= 1) m = fmaxf(m, __shfl_xor_sync(~0u, m, o));
        float l = 0.f;
        for (int j = lane; j < jcount; j += 32) {
            float e = expf(row[j] - m); row[j] = e; l += e;
        }
        for (int o = 16; o > 0; o >>= 1) l += __shfl_xor_sync(~0u, l, o);
        float inv = 1.f / l;
        for (int j = lane; j < jcount; j += 32) row[j] *= inv;
    }
    __syncthreads();
    // post-mix over heads, then bf16 hi/lo write, zero fill to i0+128
    int jendP = (i & ~63) + 128;
#pragma unroll 1
    for (int g2 = 0; g2 < 16; g2++) {
        __nv_bfloat16* ph = g_Phi + ((size_t)(b * Hh + g2) * Nn + i) * PJ;
        __nv_bfloat16* pl = g_Plo + ((size_t)(b * Hh + g2) * Nn + i) * PJ;
        const float* wp = sWpost + g2 * 16;
        for (int j = 2 * t; j < jendP; j += 512) {
            float v0 = 0.f, v1 = 0.f;
            if (j < jcount) {
                float2 a = {0.f, 0.f};
#pragma unroll
                for (int h = 0; h < 16; h++) {
                    float2 d2 = *(const float2*)&sD[h * NJ + j];
                    a.x += wp[h] * d2.x;
                    a.y += wp[h] * d2.y;
                }
                v0 = a.x;
                v1 = (j + 1 < jcount) ? a.y : 0.f;
            }
            __nv_bfloat16 h0 = __float2bfloat16(v0);
            __nv_bfloat16 h1 = __float2bfloat16(v1);
            __nv_bfloat162 hh; hh.x = h0; hh.y = h1;
            __nv_bfloat162 ll;
            ll.x = __float2bfloat16(v0 - __bfloat162float(h0));
            ll.y = __float2bfloat16(v1 - __bfloat162float(h1));
            ((__nv_bfloat162*)ph)[j >> 1] = hh;
            ((__nv_bfloat162*)pl)[j >> 1] = ll;
        }
    }
}

// ------- O_g = attn2_g @ V_g (HMMA hi/lo, per head) ------------------------
__global__ __launch_bounds__(128) void av_hmma() {
    int bh = blockIdx.y;
    int i0 = blockIdx.x * 64;
    int ntiles = i0 / 64 + 2;
    extern __shared__ __align__(128) char sm[];   // 2 x 32768
    uint32_t sb = smem_u32(sm);
    int t = threadIdx.x, lane = t & 31, w = t >> 5;
    const __nv_bfloat16* Ph = g_Phi + ((size_t)bh * Nn + i0) * PJ;
    const __nv_bfloat16* Pl = g_Plo + ((size_t)bh * Nn + i0) * PJ;
    const __nv_bfloat16* Vh = g_Vh + (size_t)bh * PJ * DHh;
    const __nv_bfloat16* Vl = g_Vl + (size_t)bh * PJ * DHh;

    auto issue = [&](int jt) {
        uint32_t st = sb + (uint32_t)(jt & 1) * 32768u;
#pragma unroll
        for (int i = 0; i < 16; i++) {
            int idx = t + i * 128;
            int tile = idx >> 9;
            int ci = idx & 511, r = ci >> 3, c = ci & 7;
            const __nv_bfloat16* g;
            if (tile == 0)      g = Ph + (size_t)r * PJ + jt * 64 + c * 8;
            else if (tile == 1) g = Pl + (size_t)r * PJ + jt * 64 + c * 8;
            else if (tile == 2) g = Vh + (size_t)(jt * 64 + r) * DHh + c * 8;
            else                g = Vl + (size_t)(jt * 64 + r) * DHh + c * 8;
            cp_async16(st + tile * 8192 + r * 128 + ((c ^ (r & 7)) << 4), g);
        }
        cp_commit();
    };

    issue(0);
    float acc[8][4] = {};
    int m0 = w * 16;
    int a_r = m0 + ((lane >> 3) & 1) * 8 + (lane & 7);
    int a_c2 = lane >> 4;
    int v_j = (lane & 7) + ((lane >> 3) & 1) * 8;
    int v_c2 = lane >> 4;
    for (int jt = 0; jt < ntiles; jt++) {
        if (jt + 1 < ntiles) { issue(jt + 1); cp_wait1(); } else cp_wait0();
        __syncthreads();
        uint32_t st = sb + (uint32_t)(jt & 1) * 32768u;
        uint32_t pH = st, pL = st + 8192, vH = st + 16384, vL = st + 24576;
#pragma unroll
        for (int kk = 0; kk < 4; kk++) {
            uint32_t fAh[4], fAl[4];
            int c = kk * 2 + a_c2;
            ldsm_x4(fAh, pH + a_r * 128 + ((c ^ (a_r & 7)) << 4));
            ldsm_x4(fAl, pL + a_r * 128 + ((c ^ (a_r & 7)) << 4));
#pragma unroll
            for (int dg = 0; dg < 4; dg++) {
                uint32_t fVh[4], fVl[4];
                int jr = kk * 16 + v_j;
                int cv = dg * 2 + v_c2;
                ldsm_x4_t(fVh, vH + jr * 128 + ((cv ^ (jr & 7)) << 4));
                ldsm_x4_t(fVl, vL + jr * 128 + ((cv ^ (jr & 7)) << 4));
                mma16816(acc[dg * 2],     fAh, fVh);
                mma16816(acc[dg * 2 + 1], fAh, fVh + 2);
                mma16816(acc[dg * 2],     fAh, fVl);
                mma16816(acc[dg * 2 + 1], fAh, fVl + 2);
                mma16816(acc[dg * 2],     fAl, fVh);
                mma16816(acc[dg * 2 + 1], fAl, fVh + 2);
            }
        }
        __syncthreads();
    }
    float* O = g_Ohd + ((size_t)bh * Nn + i0) * DHh;
    int row = m0 + (lane >> 2), cb = (lane & 3) * 2;
#pragma unroll
    for (int db = 0; db < 8; db++) {
        float2 v0 = {acc[db][0], acc[db][1]};
        float2 v1 = {acc[db][2], acc[db][3]};
        *(float2*)&O[(size_t)row * DHh + db * 8 + cb] = v0;
        *(float2*)&O[(size_t)(row + 8) * DHh + db * 8 + cb] = v1;
    }
}

// ------- gates only (post-mix already applied) -> bf16 hi/lo ---------------
__global__ __launch_bounds__(128) void mix_gate(const float* __restrict__ b_h,
                                                const float* __restrict__ b_v) {
    int rowid = blockIdx.x;             // 0..4095
    int b = rowid >> 10, n = rowid & 1023;
    int t = threadIdx.x;
#pragma unroll
    for (int k = 0; k < 8; k++) {
        int idx = t + k * 128; int g = idx >> 6, d = idx & 63;
        float a = g_Ohd[((size_t)(b * Hh + g) * Nn + n) * DHh + d];
        float hg = 1.f / (1.f + expf(-(g_hgraw[(size_t)rowid * 16 + g] + b_h[g])));
        float vg = 1.f / (1.f + expf(-(g_vgraw[(size_t)rowid * 1024 + idx] + b_v[idx])));
        float v = a * hg * vg;
        __nv_bfloat16 hi = __float2bfloat16(v);
        g_Ahi[(size_t)rowid * 1024 + idx] = hi;
        g_Alo[(size_t)rowid * 1024 + idx] = __float2bfloat16(v - __bfloat162float(hi));
    }
}

// ---------------------------------------------------------------------------
extern "C" void kernel_launch(void* const* d_in, const int* in_sizes, int n_in,
                              void* d_out, int out_size) {
    const float* x       = (const float*)d_in[0];
    const float* freqs   = (const float*)d_in[1];
    const float* Wq      = (const float*)d_in[2];
    const float* Wk      = (const float*)d_in[3];
    const float* Wv      = (const float*)d_in[4];
    const float* q_scale = (const float*)d_in[5];
    const float* k_scale = (const float*)d_in[6];
    const float* mem_k   = (const float*)d_in[7];
    const float* mem_v   = (const float*)d_in[8];
    const float* W_pre   = (const float*)d_in[9];
    const float* W_post  = (const float*)d_in[10];
    const float* W_hgate = (const float*)d_in[11];
    const float* b_hgate = (const float*)d_in[12];
    const float* W_vgate = (const float*)d_in[13];
    const float* b_vgate = (const float*)d_in[14];
    const float* Wo      = (const float*)d_in[15];
    float* out = (float*)d_out;

    float *Qraw, *Kraw, *Vraw, *vgraw;
    __nv_bfloat16 *Ahi, *Alo, *Wthi, *Wtlo;
    cudaGetSymbolAddress((void**)&Qraw, g_Qraw);
    cudaGetSymbolAddress((void**)&Kraw, g_Kraw);
    cudaGetSymbolAddress((void**)&Vraw, g_Vraw);
    cudaGetSymbolAddress((void**)&vgraw, g_vgraw);
    cudaGetSymbolAddress((void**)&Ahi, g_Ahi);
    cudaGetSymbolAddress((void**)&Alo, g_Alo);
    cudaGetSymbolAddress((void**)&Wthi, g_Wthi);
    cudaGetSymbolAddress((void**)&Wtlo, g_Wtlo);

    conv_hilo<<<ROWS * DIMm / 1024, 256>>>(x, Ahi, Alo);
    conv_w_t<<<dim3(32, 32, 5), 256>>>(Wq, Wk, Wv, W_vgate, Wo);
    hg_t<<<64, 256>>>(W_hgate);

    cudaFuncSetAttribute(mma_gemm, cudaFuncAttributeMaxDynamicSharedMemorySize, 65536);
    mma_gemm<<<dim3(DIMm / 128, ROWS / 128, 4), 256, 65536>>>(
        Ahi, Alo, Wthi, Wtlo, 0, Qraw, Kraw, Vraw, vgraw);
    hgate_warp<<<ROWS / 4, 128>>>(x);

    int warps = Bb * Nn * Hh + Bb * Hh * Mm;
    prep_kernel<<<(warps + 7) / 8, 256>>>(freqs, q_scale, k_scale, mem_k, mem_v);

    dots_hmma<<<dim3(17, 16, 64), 128>>>();

    size_t smem_bytes = (16 * NJ + 16 * 64 + 512) * sizeof(float);
    cudaFuncSetAttribute(softmax_kernel, cudaFuncAttributeMaxDynamicSharedMemorySize,
                         (int)smem_bytes);
    softmax_kernel<<<dim3(Nn, Bb), 256, smem_bytes>>>(W_pre, W_post);

    cudaFuncSetAttribute(av_hmma, cudaFuncAttributeMaxDynamicSharedMemorySize, 65536);
    av_hmma<<<dim3(16, 64), 128, 65536>>>();

    mix_gate<<<ROWS, 128>>>(b_hgate, b_vgate);

    mma_gemm<<<dim3(DIMm / 128, ROWS / 128, 1), 256, 65536>>>(
        Ahi, Alo, Wthi, Wtlo, 4, out, out, out, out);
}

// round 6
// speedup vs baseline: 3.7573x; 1.0191x over previous
#include <cuda_runtime.h>
#include <cuda_bf16.h>
#include <cuda_fp16.h>
#include <math.h>
#include <float.h>
#include <stdint.h>

#define Bb   4
#define Nn   1024
#define DIMm 1024
#define Hh   16
#define DHh  64
#define Mm   16
#define NJ   1040          // M + N
#define PJ   1088          // padded kv length (multiple of 64)
#define ROWS 4096          // B*N
#define QK_SCALE 10.0f

// ===================== scratch =============================================
__device__ float g_Qraw[(size_t)ROWS * DIMm];
__device__ float g_Kraw[(size_t)ROWS * DIMm];
__device__ float g_Vraw[(size_t)ROWS * DIMm];
__device__ float g_vgraw[(size_t)ROWS * DIMm];
__device__ float g_hgraw[(size_t)ROWS * Hh];
__device__ float g_dots[(size_t)64 * Nn * NJ];
__device__ float g_Ohd[(size_t)64 * Nn * DHh];
__device__ float g_Whgt[16 * 1024];
__device__ __nv_bfloat16 g_Qh[(size_t)64 * Nn * DHh];
__device__ __nv_bfloat16 g_Ql[(size_t)64 * Nn * DHh];
__device__ __nv_bfloat16 g_Kh[(size_t)64 * PJ * DHh];   // pad rows stay zero
__device__ __nv_bfloat16 g_Kl[(size_t)64 * PJ * DHh];
__device__ __half g_Vh16[(size_t)64 * PJ * DHh];        // pad rows stay zero
__device__ __half g_Vl16[(size_t)64 * PJ * DHh];
__device__ __half g_P16[(size_t)64 * Nn * PJ];
__device__ __nv_bfloat16 g_Ahi[(size_t)ROWS * DIMm];
__device__ __nv_bfloat16 g_Alo[(size_t)ROWS * DIMm];
__device__ __nv_bfloat16 g_Wthi[(size_t)5 * DIMm * DIMm];
__device__ __nv_bfloat16 g_Wtlo[(size_t)5 * DIMm * DIMm];

// ===================== PTX helpers (base ISA only) =========================
__device__ __forceinline__ uint32_t smem_u32(const void* p) {
    uint32_t a;
    asm("{ .reg .u64 tmp; cvta.to.shared.u64 tmp, %1; cvt.u32.u64 %0, tmp; }"
        : "=r"(a) : "l"(p));
    return a;
}
__device__ __forceinline__ void cp_async16(uint32_t s, const void* g) {
    asm volatile("cp.async.cg.shared.global [%0], [%1], 16;" :: "r"(s), "l"(g));
}
__device__ __forceinline__ void cp_commit() {
    asm volatile("cp.async.commit_group;" ::: "memory");
}
__device__ __forceinline__ void cp_wait1() {
    asm volatile("cp.async.wait_group 1;" ::: "memory");
}
__device__ __forceinline__ void cp_wait0() {
    asm volatile("cp.async.wait_group 0;" ::: "memory");
}
__device__ __forceinline__ void ldsm_x4(uint32_t* r, uint32_t addr) {
    asm volatile("ldmatrix.sync.aligned.m8n8.x4.shared.b16 {%0,%1,%2,%3}, [%4];"
                 : "=r"(r[0]), "=r"(r[1]), "=r"(r[2]), "=r"(r[3]) : "r"(addr));
}
__device__ __forceinline__ void ldsm_x4_t(uint32_t* r, uint32_t addr) {
    asm volatile("ldmatrix.sync.aligned.m8n8.x4.trans.shared.b16 {%0,%1,%2,%3}, [%4];"
                 : "=r"(r[0]), "=r"(r[1]), "=r"(r[2]), "=r"(r[3]) : "r"(addr));
}
__device__ __forceinline__ void mma16816(float* d, const uint32_t* a, const uint32_t* b) {
    asm volatile(
        "mma.sync.aligned.m16n8k16.row.col.f32.bf16.bf16.f32 "
        "{%0,%1,%2,%3}, {%4,%5,%6,%7}, {%8,%9}, {%0,%1,%2,%3};"
        : "+f"(d[0]), "+f"(d[1]), "+f"(d[2]), "+f"(d[3])
        : "r"(a[0]), "r"(a[1]), "r"(a[2]), "r"(a[3]), "r"(b[0]), "r"(b[1]));
}
__device__ __forceinline__ void mma16816h(float* d, const uint32_t* a, const uint32_t* b) {
    asm volatile(
        "mma.sync.aligned.m16n8k16.row.col.f32.f16.f16.f32 "
        "{%0,%1,%2,%3}, {%4,%5,%6,%7}, {%8,%9}, {%0,%1,%2,%3};"
        : "+f"(d[0]), "+f"(d[1]), "+f"(d[2]), "+f"(d[3])
        : "r"(a[0]), "r"(a[1]), "r"(a[2]), "r"(a[3]), "r"(b[0]), "r"(b[1]));
}

// ===================== convert kernels =====================================
__global__ void conv_hilo(const float* __restrict__ src,
                          __nv_bfloat16* __restrict__ hi,
                          __nv_bfloat16* __restrict__ lo) {
    int i = blockIdx.x * 256 + threadIdx.x;
    float4 v = ((const float4*)src)[i];
    float f[4] = {v.x, v.y, v.z, v.w};
    __nv_bfloat16 h[4], l[4];
#pragma unroll
    for (int k = 0; k < 4; k++) {
        h[k] = __float2bfloat16(f[k]);
        l[k] = __float2bfloat16(f[k] - __bfloat162float(h[k]));
    }
    __nv_bfloat162 p0, p1, q0, q1;
    p0.x = h[0]; p0.y = h[1]; p1.x = h[2]; p1.y = h[3];
    q0.x = l[0]; q0.y = l[1]; q1.x = l[2]; q1.y = l[3];
    ((__nv_bfloat162*)hi)[i * 2] = p0; ((__nv_bfloat162*)hi)[i * 2 + 1] = p1;
    ((__nv_bfloat162*)lo)[i * 2] = q0; ((__nv_bfloat162*)lo)[i * 2 + 1] = q1;
}

__global__ void conv_w_t(const float* __restrict__ W0, const float* __restrict__ W1,
                         const float* __restrict__ W2, const float* __restrict__ W3,
                         const float* __restrict__ W4) {
    const float* Ws[5] = {W0, W1, W2, W3, W4};
    const float* W = Ws[blockIdx.z];
    __nv_bfloat16* hi = g_Wthi + (size_t)blockIdx.z * DIMm * DIMm;
    __nv_bfloat16* lo = g_Wtlo + (size_t)blockIdx.z * DIMm * DIMm;
    __shared__ float tile[32][33];
    int k0 = blockIdx.y * 32, n0 = blockIdx.x * 32;
    int c = threadIdx.x & 31, r8 = threadIdx.x >> 5;
#pragma unroll
    for (int i = 0; i < 4; i++) {
        int r = r8 + i * 8;
        tile[r][c] = W[(size_t)(k0 + r) * DIMm + n0 + c];
    }
    __syncthreads();
#pragma unroll
    for (int i = 0; i < 4; i++) {
        int r = r8 + i * 8;
        float v = tile[c][r];
        __nv_bfloat16 h = __float2bfloat16(v);
        hi[(size_t)(n0 + r) * DIMm + k0 + c] = h;
        lo[(size_t)(n0 + r) * DIMm + k0 + c] = __float2bfloat16(v - __bfloat162float(h));
    }
}

__global__ void hg_t(const float* __restrict__ W) {
    int idx = blockIdx.x * 256 + threadIdx.x;   // 16384
    int h = idx >> 10, k = idx & 1023;
    g_Whgt[idx] = W[k * 16 + h];
}

// ===================== HMMA projection/output GEMM =========================
__global__ __launch_bounds__(256)
void mma_gemm(const __nv_bfloat16* __restrict__ Ahi, const __nv_bfloat16* __restrict__ Alo,
              const __nv_bfloat16* __restrict__ WthiB, const __nv_bfloat16* __restrict__ WtloB,
              int wbase,
              float* __restrict__ C0, float* __restrict__ C1,
              float* __restrict__ C2, float* __restrict__ C3) {
    extern __shared__ __align__(1024) char smem[];
    uint32_t sbase = smem_u32(smem);
    int z = blockIdx.z;
    const __nv_bfloat16* Bh = WthiB + (size_t)(wbase + z) * DIMm * DIMm;
    const __nv_bfloat16* Bl = WtloB + (size_t)(wbase + z) * DIMm * DIMm;
    float* C = (z == 0) ? C0 : (z == 1) ? C1 : (z == 2) ? C2 : C3;

    int t = threadIdx.x;
    int lane = t & 31, w = t >> 5;
    int wm = w >> 2, wn = w & 3;
    int i0 = blockIdx.y * 128, n0 = blockIdx.x * 128;

    float acc[4][4][4] = {};

    int a_rl = ((lane >> 3) & 1) * 8 + (lane & 7);
    int a_ch = lane >> 4;
    int b_nl = (lane & 7) + ((lane >> 4) & 1) * 8;
    int b_ch = (lane >> 3) & 1;

    auto issue_load = [&](int ks) {
        uint32_t stage = sbase + (uint32_t)(ks & 1) * 32768u;
        int k0 = ks * 32;
#pragma unroll
        for (int i = 0; i < 8; i++) {
            int tile = i >> 1;
            int ci = ((i & 1) << 8) + t;
            int r = ci >> 2, c = ci & 3;
            const __nv_bfloat16* src = (tile == 0) ? Ahi : (tile == 1) ? Alo
                                     : (tile == 2) ? Bh : Bl;
            int rb = (tile < 2) ? i0 : n0;
            const __nv_bfloat16* g = src + (size_t)(rb + r) * DIMm + k0 + c * 8;
            uint32_t s = stage + (uint32_t)(tile * 8192 + r * 64 +
                          (((c ^ ((r >> 1) & 3))) << 4));
            cp_async16(s, g);
        }
        cp_commit();
    };

    issue_load(0);
    const int NS = DIMm / 32;
    for (int ks = 0; ks < NS; ks++) {
        if (ks + 1 < NS) issue_load(ks + 1);
        if (ks + 1 < NS) cp_wait1(); else cp_wait0();
        __syncthreads();
        uint32_t sb = sbase + (uint32_t)(ks & 1) * 32768u;
        uint32_t aH = sb, aL = sb + 8192, bH = sb + 16384, bL = sb + 24576;
#pragma unroll
        for (int kk = 0; kk < 2; kk++) {
            int c0 = kk * 2;
            uint32_t fBh[2][4], fBl[2][4], fA[4][4];
#pragma unroll
            for (int ng = 0; ng < 2; ng++) {
                int n = wn * 32 + ng * 16 + b_nl;
                int c = c0 + b_ch;
                uint32_t off = (uint32_t)(n * 64 + ((c ^ ((n >> 1) & 3)) << 4));
                ldsm_x4(fBh[ng], bH + off);
                ldsm_x4(fBl[ng], bL + off);
            }
#pragma unroll
            for (int mt = 0; mt < 4; mt++) {
                int r = wm * 64 + mt * 16 + a_rl;
                int c = c0 + a_ch;
                uint32_t off = (uint32_t)(r * 64 + ((c ^ ((r >> 1) & 3)) << 4));
                ldsm_x4(fA[mt], aH + off);
            }
#pragma unroll
            for (int mt = 0; mt < 4; mt++)
#pragma unroll
                for (int nt = 0; nt < 4; nt++) {
                    mma16816(acc[mt][nt], fA[mt], &fBh[nt >> 1][(nt & 1) * 2]);
                    mma16816(acc[mt][nt], fA[mt], &fBl[nt >> 1][(nt & 1) * 2]);
                }
#pragma unroll
            for (int mt = 0; mt < 4; mt++) {
                int r = wm * 64 + mt * 16 + a_rl;
                int c = c0 + a_ch;
                uint32_t off = (uint32_t)(r * 64 + ((c ^ ((r >> 1) & 3)) << 4));
                ldsm_x4(fA[mt], aL + off);
            }
#pragma unroll
            for (int mt = 0; mt < 4; mt++)
#pragma unroll
                for (int nt = 0; nt < 4; nt++)
                    mma16816(acc[mt][nt], fA[mt], &fBh[nt >> 1][(nt & 1) * 2]);
        }
        __syncthreads();
    }

    int row0 = i0 + wm * 64 + (lane >> 2);
    int col0 = n0 + wn * 32 + (lane & 3) * 2;
#pragma unroll
    for (int mt = 0; mt < 4; mt++)
#pragma unroll
        for (int nt = 0; nt < 4; nt++) {
            int r = row0 + mt * 16, cc = col0 + nt * 8;
            float2 v0 = {acc[mt][nt][0], acc[mt][nt][1]};
            float2 v1 = {acc[mt][nt][2], acc[mt][nt][3]};
            *(float2*)&C[(size_t)r * DIMm + cc] = v0;
            *(float2*)&C[(size_t)(r + 8) * DIMm + cc] = v1;
        }
}

// ---------------- head-gate: warp per row ----------------------------------
__global__ __launch_bounds__(128) void hgate_warp(const float* __restrict__ x) {
    int w = blockIdx.x * 4 + (threadIdx.x >> 5);
    int l = threadIdx.x & 31;
    float acc[16] = {};
    const float* xr = x + (size_t)w * 1024;
#pragma unroll
    for (int i = 0; i < 8; i++) {
        float4 xv = *(const float4*)&xr[i * 128 + l * 4];
#pragma unroll
        for (int h = 0; h < 16; h++) {
            float4 wv = *(const float4*)&g_Whgt[h * 1024 + i * 128 + l * 4];
            acc[h] += xv.x * wv.x + xv.y * wv.y + xv.z * wv.z + xv.w * wv.w;
        }
    }
#pragma unroll
    for (int h = 0; h < 16; h++)
#pragma unroll
        for (int o = 16; o > 0; o >>= 1) acc[h] += __shfl_xor_sync(~0u, acc[h], o);
    if (l == 0) {
#pragma unroll
        for (int h = 0; h < 16; h++) g_hgraw[(size_t)w * 16 + h] = acc[h];
    }
}

// ---------------- l2norm + scale + rope -> split layouts -------------------
__device__ __forceinline__ void wr_hl(__nv_bfloat16* H, __nv_bfloat16* L,
                                      size_t rowoff, int lane, float2 v) {
    __nv_bfloat16 hx = __float2bfloat16(v.x), hy = __float2bfloat16(v.y);
    __nv_bfloat162 hh; hh.x = hx; hh.y = hy;
    __nv_bfloat162 ll;
    ll.x = __float2bfloat16(v.x - __bfloat162float(hx));
    ll.y = __float2bfloat16(v.y - __bfloat162float(hy));
    ((__nv_bfloat162*)(H + rowoff))[lane] = hh;
    ((__nv_bfloat162*)(L + rowoff))[lane] = ll;
}
__device__ __forceinline__ void wr_hl16(__half* H, __half* L,
                                        size_t rowoff, int lane, float2 v) {
    __half hx = __float2half(v.x), hy = __float2half(v.y);
    __half2 hh; hh.x = hx; hh.y = hy;
    __half2 ll;
    ll.x = __float2half(v.x - __half2float(hx));
    ll.y = __float2half(v.y - __half2float(hy));
    ((__half2*)(H + rowoff))[lane] = hh;
    ((__half2*)(L + rowoff))[lane] = ll;
}

__global__ void prep_kernel(const float* __restrict__ freqs,
                            const float* __restrict__ q_scale,
                            const float* __restrict__ k_scale,
                            const float* __restrict__ mem_k,
                            const float* __restrict__ mem_v) {
    int w = (blockIdx.x * blockDim.x + threadIdx.x) >> 5;
    int lane = threadIdx.x & 31;
    const int MAIN = Bb * Nn * Hh;
    if (w < MAIN) {
        int b = w / (Nn * Hh); int r = w % (Nn * Hh);
        int n = r / Hh; int h = r % Hh;
        size_t src = (size_t)(b * Nn + n) * DIMm + h * DHh;
        float2 q2 = ((const float2*)&g_Qraw[src])[lane];
        float2 k2 = ((const float2*)&g_Kraw[src])[lane];
        float2 v2 = ((const float2*)&g_Vraw[src])[lane];
        float ssq = q2.x * q2.x + q2.y * q2.y;
        float ssk = k2.x * k2.x + k2.y * k2.y;
        for (int o = 16; o > 0; o >>= 1) {
            ssq += __shfl_xor_sync(~0u, ssq, o);
            ssk += __shfl_xor_sync(~0u, ssk, o);
        }
        float invq = 1.0f / fmaxf(sqrtf(ssq), 1e-12f);
        float invk = 1.0f / fmaxf(sqrtf(ssk), 1e-12f);
        float sqx = q_scale[h * DHh + 2 * lane], sqy = q_scale[h * DHh + 2 * lane + 1];
        float skx = k_scale[h * DHh + 2 * lane], sky = k_scale[h * DHh + 2 * lane + 1];
        float qx = q2.x * invq * sqx, qy = q2.y * invq * sqy;
        float kx = k2.x * invk * skx, ky = k2.y * invk * sky;
        float f = freqs[n * DHh + 2 * lane];
        float cf = cosf(f), sf = sinf(f);
        float2 qo = {qx * cf - qy * sf, qy * cf + qx * sf};
        float2 ko = {kx * cf - ky * sf, ky * cf + kx * sf};
        int bh = b * Hh + h;
        wr_hl(g_Qh, g_Ql, ((size_t)bh * Nn + n) * DHh, lane, qo);
        wr_hl(g_Kh, g_Kl, ((size_t)bh * PJ + Mm + n) * DHh, lane, ko);
        wr_hl16(g_Vh16, g_Vl16, ((size_t)bh * PJ + Mm + n) * DHh, lane, v2);
    } else {
        int w2 = w - MAIN;
        if (w2 < Bb * Hh * Mm) {
            int b = w2 / (Hh * Mm); int r = w2 % (Hh * Mm);
            int h = r / Mm; int m = r % Mm;
            float2 mk = ((const float2*)&mem_k[(size_t)(h * Mm + m) * DHh])[lane];
            float2 mv = ((const float2*)&mem_v[(size_t)(h * Mm + m) * DHh])[lane];
            float ss = mk.x * mk.x + mk.y * mk.y;
            for (int o = 16; o > 0; o >>= 1) ss += __shfl_xor_sync(~0u, ss, o);
            float inv = 1.0f / fmaxf(sqrtf(ss), 1e-12f);
            float2 ko = {mk.x * inv * k_scale[h * DHh + 2 * lane],
                         mk.y * inv * k_scale[h * DHh + 2 * lane + 1]};
            int bh = b * Hh + h;
            wr_hl(g_Kh, g_Kl, ((size_t)bh * PJ + m) * DHh, lane, ko);
            wr_hl16(g_Vh16, g_Vl16, ((size_t)bh * PJ + m) * DHh, lane, mv);
        }
    }
}

// ---------------- dots = Q K^T (HMMA bf16 hi/lo, raw scores) ---------------
__global__ __launch_bounds__(128) void dots_hmma() {
    int bh = blockIdx.z;
    int i0 = blockIdx.y * 64, j0 = blockIdx.x * 64;
    if (j0 >= i0 + 80) return;
    __shared__ __align__(128) char sm[32768];
    uint32_t sb = smem_u32(sm);
    int t = threadIdx.x, lane = t & 31, w = t >> 5;
    const __nv_bfloat16* Qh = g_Qh + ((size_t)bh * Nn + i0) * DHh;
    const __nv_bfloat16* Ql = g_Ql + ((size_t)bh * Nn + i0) * DHh;
    const __nv_bfloat16* Kh = g_Kh + ((size_t)bh * PJ + j0) * DHh;
    const __nv_bfloat16* Kl = g_Kl + ((size_t)bh * PJ + j0) * DHh;
#pragma unroll
    for (int i = 0; i < 16; i++) {
        int idx = t + i * 128;
        int tile = idx >> 9;
        int ci = idx & 511, r = ci >> 3, c = ci & 7;
        const __nv_bfloat16* src = (tile == 0) ? Qh : (tile == 1) ? Ql
                                 : (tile == 2) ? Kh : Kl;
        cp_async16(sb + tile * 8192 + r * 128 + ((c ^ (r & 7)) << 4),
                   src + (size_t)r * DHh + c * 8);
    }
    cp_commit(); cp_wait0();
    __syncthreads();
    int m0 = w * 16;
    float acc[8][4] = {};
    int a_r = m0 + ((lane >> 3) & 1) * 8 + (lane & 7);
    int a_c2 = lane >> 4;
    int b_r = (lane & 7) + ((lane >> 4) & 1) * 8;
    int b_c2 = (lane >> 3) & 1;
    uint32_t aH = sb, aL = sb + 8192, bH = sb + 16384, bL = sb + 24576;
#pragma unroll
    for (int pass = 0; pass < 3; pass++) {
        uint32_t at = (pass == 2) ? aL : aH;
        uint32_t bt = (pass == 1) ? bL : bH;
#pragma unroll
        for (int kk = 0; kk < 4; kk++) {
            uint32_t fA[4];
            int c = kk * 2 + a_c2;
            ldsm_x4(fA, at + a_r * 128 + ((c ^ (a_r & 7)) << 4));
#pragma unroll
            for (int ng = 0; ng < 4; ng++) {
                uint32_t fB[4];
                int n = ng * 16 + b_r;
                int cb = kk * 2 + b_c2;
                ldsm_x4(fB, bt + n * 128 + ((cb ^ (n & 7)) << 4));
                mma16816(acc[ng * 2], fA, fB);
                mma16816(acc[ng * 2 + 1], fA, fB + 2);
            }
        }
    }
    int row = i0 + m0 + (lane >> 2);
    int cb = (lane & 3) * 2;
    float* D = g_dots + (size_t)bh * Nn * NJ;
#pragma unroll
    for (int nb = 0; nb < 8; nb++) {
        int col = j0 + nb * 8 + cb;
        if (col < NJ) {
            float2 v0 = {acc[nb][0], acc[nb][1]};
            float2 v1 = {acc[nb][2], acc[nb][3]};
            *(float2*)&D[(size_t)row * NJ + col] = v0;
            *(float2*)&D[(size_t)(row + 8) * NJ + col] = v1;
        }
    }
}

// --- fused: pre-mix (W_pre*QK_SCALE) -> softmax -> post-mix -> fp16 P ------
__global__ void softmax_kernel(const float* __restrict__ W_pre,
                               const float* __restrict__ W_post) {
    extern __shared__ float smemf[];
    float* sD = smemf;                 // 16 * NJ
    float* sT = sD + 16 * NJ;          // 16 * 64
    float* sWpre = sT + 16 * 64;       // 256
    float* sWpost = sWpre + 256;       // 256
    int t = threadIdx.x;
    int i = blockIdx.x, b = blockIdx.y;
    sWpre[t] = W_pre[t] * QK_SCALE;
    sWpost[t] = W_post[t];
    int jcount = i + 17;
    __syncthreads();
    int g = t >> 4, q = t & 15;
    for (int j0 = 0; j0 < jcount; j0 += 64) {
        for (int idx = t; idx < 1024; idx += 256) {
            int h = idx >> 6, jj = idx & 63, j = j0 + jj;
            sT[idx] = (j < jcount)
                ? g_dots[((size_t)(b * Hh + h) * Nn + i) * NJ + j] : 0.f;
        }
        __syncthreads();
#pragma unroll
        for (int u = 0; u < 4; u++) {
            int jj = q * 4 + u, j = j0 + jj;
            if (j < jcount) {
                float a = 0.f;
#pragma unroll
                for (int h = 0; h < 16; h++) a += sWpre[g * 16 + h] * sT[h * 64 + jj];
                sD[g * NJ + j] = a;
            }
        }
        __syncthreads();
    }
    int warp = t >> 5, lane = t & 31;
    for (int gg = warp; gg < 16; gg += 8) {
        float* row = sD + gg * NJ;
        float m = -FLT_MAX;
        for (int j = lane; j < jcount; j += 32) m = fmaxf(m, row[j]);
        for (int o = 16; o > 0; o >>= 1) m = fmaxf(m, __shfl_xor_sync(~0u, m, o));
        float l = 0.f;
        for (int j = lane; j < jcount; j += 32) {
            float e = expf(row[j] - m); row[j] = e; l += e;
        }
        for (int o = 16; o > 0; o >>= 1) l += __shfl_xor_sync(~0u, l, o);
        float inv = 1.f / l;
        for (int j = lane; j < jcount; j += 32) row[j] *= inv;
    }
    __syncthreads();
    // post-mix over heads, then fp16 write, zero fill to i0+128
    int jendP = (i & ~63) + 128;
#pragma unroll 1
    for (int g2 = 0; g2 < 16; g2++) {
        __half* ph = g_P16 + ((size_t)(b * Hh + g2) * Nn + i) * PJ;
        const float* wp = sWpost + g2 * 16;
        for (int j = 2 * t; j < jendP; j += 512) {
            float v0 = 0.f, v1 = 0.f;
            if (j < jcount) {
                float2 a = {0.f, 0.f};
#pragma unroll
                for (int h = 0; h < 16; h++) {
                    float2 d2 = *(const float2*)&sD[h * NJ + j];
                    a.x += wp[h] * d2.x;
                    a.y += wp[h] * d2.y;
                }
                v0 = a.x;
                v1 = (j + 1 < jcount) ? a.y : 0.f;
            }
            __half2 hh; hh.x = __float2half(v0); hh.y = __float2half(v1);
            ((__half2*)ph)[j >> 1] = hh;
        }
    }
}

// ------- O_g = P_g @ V_g (fp16: P single, V hi/lo; 2 passes) ---------------
__global__ __launch_bounds__(128) void av_hmma() {
    int bh = blockIdx.y;
    int i0 = blockIdx.x * 64;
    int ntiles = i0 / 64 + 2;
    extern __shared__ __align__(128) char sm[];   // 2 x 24576
    uint32_t sb = smem_u32(sm);
    int t = threadIdx.x, lane = t & 31, w = t >> 5;
    const __half* P = g_P16 + ((size_t)bh * Nn + i0) * PJ;
    const __half* Vh = g_Vh16 + (size_t)bh * PJ * DHh;
    const __half* Vl = g_Vl16 + (size_t)bh * PJ * DHh;

    auto issue = [&](int jt) {
        uint32_t st = sb + (uint32_t)(jt & 1) * 24576u;
#pragma unroll
        for (int i = 0; i < 12; i++) {
            int idx = t + i * 128;
            int tile = idx >> 9;
            int ci = idx & 511, r = ci >> 3, c = ci & 7;
            const __half* g;
            if (tile == 0)      g = P + (size_t)r * PJ + jt * 64 + c * 8;
            else if (tile == 1) g = Vh + (size_t)(jt * 64 + r) * DHh + c * 8;
            else                g = Vl + (size_t)(jt * 64 + r) * DHh + c * 8;
            cp_async16(st + tile * 8192 + r * 128 + ((c ^ (r & 7)) << 4), g);
        }
        cp_commit();
    };

    issue(0);
    float acc[8][4] = {};
    int m0 = w * 16;
    int a_r = m0 + ((lane >> 3) & 1) * 8 + (lane & 7);
    int a_c2 = lane >> 4;
    int v_j = (lane & 7) + ((lane >> 3) & 1) * 8;
    int v_c2 = lane >> 4;
    for (int jt = 0; jt < ntiles; jt++) {
        if (jt + 1 < ntiles) { issue(jt + 1); cp_wait1(); } else cp_wait0();
        __syncthreads();
        uint32_t st = sb + (uint32_t)(jt & 1) * 24576u;
        uint32_t pA = st, vH = st + 8192, vL = st + 16384;
#pragma unroll
        for (int kk = 0; kk < 4; kk++) {
            uint32_t fA[4];
            int c = kk * 2 + a_c2;
            ldsm_x4(fA, pA + a_r * 128 + ((c ^ (a_r & 7)) << 4));
#pragma unroll
            for (int dg = 0; dg < 4; dg++) {
                uint32_t fVh[4], fVl[4];
                int jr = kk * 16 + v_j;
                int cv = dg * 2 + v_c2;
                ldsm_x4_t(fVh, vH + jr * 128 + ((cv ^ (jr & 7)) << 4));
                ldsm_x4_t(fVl, vL + jr * 128 + ((cv ^ (jr & 7)) << 4));
                mma16816h(acc[dg * 2],     fA, fVh);
                mma16816h(acc[dg * 2 + 1], fA, fVh + 2);
                mma16816h(acc[dg * 2],     fA, fVl);
                mma16816h(acc[dg * 2 + 1], fA, fVl + 2);
            }
        }
        __syncthreads();
    }
    float* O = g_Ohd + ((size_t)bh * Nn + i0) * DHh;
    int row = m0 + (lane >> 2), cb = (lane & 3) * 2;
#pragma unroll
    for (int db = 0; db < 8; db++) {
        float2 v0 = {acc[db][0], acc[db][1]};
        float2 v1 = {acc[db][2], acc[db][3]};
        *(float2*)&O[(size_t)row * DHh + db * 8 + cb] = v0;
        *(float2*)&O[(size_t)(row + 8) * DHh + db * 8 + cb] = v1;
    }
}

// ------- gates only (post-mix already applied) -> bf16 hi/lo ---------------
__global__ __launch_bounds__(128) void mix_gate(const float* __restrict__ b_h,
                                                const float* __restrict__ b_v) {
    int rowid = blockIdx.x;             // 0..4095
    int b = rowid >> 10, n = rowid & 1023;
    int t = threadIdx.x;
#pragma unroll
    for (int k = 0; k < 8; k++) {
        int idx = t + k * 128; int g = idx >> 6, d = idx & 63;
        float a = g_Ohd[((size_t)(b * Hh + g) * Nn + n) * DHh + d];
        float hg = 1.f / (1.f + expf(-(g_hgraw[(size_t)rowid * 16 + g] + b_h[g])));
        float vg = 1.f / (1.f + expf(-(g_vgraw[(size_t)rowid * 1024 + idx] + b_v[idx])));
        float v = a * hg * vg;
        __nv_bfloat16 hi = __float2bfloat16(v);
        g_Ahi[(size_t)rowid * 1024 + idx] = hi;
        g_Alo[(size_t)rowid * 1024 + idx] = __float2bfloat16(v - __bfloat162float(hi));
    }
}

// ---------------------------------------------------------------------------
extern "C" void kernel_launch(void* const* d_in, const int* in_sizes, int n_in,
                              void* d_out, int out_size) {
    const float* x       = (const float*)d_in[0];
    const float* freqs   = (const float*)d_in[1];
    const float* Wq      = (const float*)d_in[2];
    const float* Wk      = (const float*)d_in[3];
    const float* Wv      = (const float*)d_in[4];
    const float* q_scale = (const float*)d_in[5];
    const float* k_scale = (const float*)d_in[6];
    const float* mem_k   = (const float*)d_in[7];
    const float* mem_v   = (const float*)d_in[8];
    const float* W_pre   = (const float*)d_in[9];
    const float* W_post  = (const float*)d_in[10];
    const float* W_hgate = (const float*)d_in[11];
    const float* b_hgate = (const float*)d_in[12];
    const float* W_vgate = (const float*)d_in[13];
    const float* b_vgate = (const float*)d_in[14];
    const float* Wo      = (const float*)d_in[15];
    float* out = (float*)d_out;

    float *Qraw, *Kraw, *Vraw, *vgraw;
    __nv_bfloat16 *Ahi, *Alo, *Wthi, *Wtlo;
    cudaGetSymbolAddress((void**)&Qraw, g_Qraw);
    cudaGetSymbolAddress((void**)&Kraw, g_Kraw);
    cudaGetSymbolAddress((void**)&Vraw, g_Vraw);
    cudaGetSymbolAddress((void**)&vgraw, g_vgraw);
    cudaGetSymbolAddress((void**)&Ahi, g_Ahi);
    cudaGetSymbolAddress((void**)&Alo, g_Alo);
    cudaGetSymbolAddress((void**)&Wthi, g_Wthi);
    cudaGetSymbolAddress((void**)&Wtlo, g_Wtlo);

    conv_hilo<<<ROWS * DIMm / 1024, 256>>>(x, Ahi, Alo);
    conv_w_t<<<dim3(32, 32, 5), 256>>>(Wq, Wk, Wv, W_vgate, Wo);
    hg_t<<<64, 256>>>(W_hgate);

    cudaFuncSetAttribute(mma_gemm, cudaFuncAttributeMaxDynamicSharedMemorySize, 65536);
    mma_gemm<<<dim3(DIMm / 128, ROWS / 128, 4), 256, 65536>>>(
        Ahi, Alo, Wthi, Wtlo, 0, Qraw, Kraw, Vraw, vgraw);
    hgate_warp<<<ROWS / 4, 128>>>(x);

    int warps = Bb * Nn * Hh + Bb * Hh * Mm;
    prep_kernel<<<(warps + 7) / 8, 256>>>(freqs, q_scale, k_scale, mem_k, mem_v);

    dots_hmma<<<dim3(17, 16, 64), 128>>>();

    size_t smem_bytes = (16 * NJ + 16 * 64 + 512) * sizeof(float);
    cudaFuncSetAttribute(softmax_kernel, cudaFuncAttributeMaxDynamicSharedMemorySize,
                         (int)smem_bytes);
    softmax_kernel<<<dim3(Nn, Bb), 256, smem_bytes>>>(W_pre, W_post);

    cudaFuncSetAttribute(av_hmma, cudaFuncAttributeMaxDynamicSharedMemorySize, 49152);
    av_hmma<<<dim3(16, 64), 128, 49152>>>();

    mix_gate<<<ROWS, 128>>>(b_hgate, b_vgate);

    mma_gemm<<<dim3(DIMm / 128, ROWS / 128, 1), 256, 65536>>>(
        Ahi, Alo, Wthi, Wtlo, 4, out, out, out, out);
}

// round 7
// speedup vs baseline: 4.9404x; 1.3149x over previous
#include <cuda_runtime.h>
#include <cuda_bf16.h>
#include <cuda_fp16.h>
#include <math.h>
#include <float.h>
#include <stdint.h>

#define Bb   4
#define Nn   1024
#define DIMm 1024
#define Hh   16
#define DHh  64
#define Mm   16
#define NJ   1040          // M + N
#define PJ   1088          // padded kv length (multiple of 64)
#define ROWS 4096          // B*N
#define QK_SCALE 10.0f

// ===================== scratch =============================================
__device__ float g_Qraw[(size_t)ROWS * DIMm];
__device__ float g_Kraw[(size_t)ROWS * DIMm];
__device__ float g_Vraw[(size_t)ROWS * DIMm];
__device__ float g_vgraw[(size_t)ROWS * DIMm];
__device__ float g_hgraw[(size_t)ROWS * Hh];
__device__ float g_dots[(size_t)64 * Nn * NJ];
__device__ float g_Ohd[(size_t)64 * Nn * DHh];
__device__ float g_Whgt[16 * 1024];
__device__ __nv_bfloat16 g_Qh[(size_t)64 * Nn * DHh];
__device__ __nv_bfloat16 g_Ql[(size_t)64 * Nn * DHh];
__device__ __nv_bfloat16 g_Kh[(size_t)64 * PJ * DHh];   // pad rows stay zero
__device__ __nv_bfloat16 g_Kl[(size_t)64 * PJ * DHh];
__device__ __half g_Vh16[(size_t)64 * PJ * DHh];        // pad rows stay zero
__device__ __half g_Vl16[(size_t)64 * PJ * DHh];
__device__ __half g_P16[(size_t)64 * Nn * PJ];
__device__ __nv_bfloat16 g_Ahi[(size_t)ROWS * DIMm];
__device__ __nv_bfloat16 g_Alo[(size_t)ROWS * DIMm];
__device__ __nv_bfloat16 g_Wthi[(size_t)5 * DIMm * DIMm];
__device__ __nv_bfloat16 g_Wtlo[(size_t)5 * DIMm * DIMm];

// ===================== PTX helpers (base ISA only) =========================
__device__ __forceinline__ uint32_t smem_u32(const void* p) {
    uint32_t a;
    asm("{ .reg .u64 tmp; cvta.to.shared.u64 tmp, %1; cvt.u32.u64 %0, tmp; }"
        : "=r"(a) : "l"(p));
    return a;
}
__device__ __forceinline__ void cp_async16(uint32_t s, const void* g) {
    asm volatile("cp.async.cg.shared.global [%0], [%1], 16;" :: "r"(s), "l"(g));
}
__device__ __forceinline__ void cp_commit() {
    asm volatile("cp.async.commit_group;" ::: "memory");
}
__device__ __forceinline__ void cp_wait1() {
    asm volatile("cp.async.wait_group 1;" ::: "memory");
}
__device__ __forceinline__ void cp_wait0() {
    asm volatile("cp.async.wait_group 0;" ::: "memory");
}
__device__ __forceinline__ void ldsm_x4(uint32_t* r, uint32_t addr) {
    asm volatile("ldmatrix.sync.aligned.m8n8.x4.shared.b16 {%0,%1,%2,%3}, [%4];"
                 : "=r"(r[0]), "=r"(r[1]), "=r"(r[2]), "=r"(r[3]) : "r"(addr));
}
__device__ __forceinline__ void ldsm_x4_t(uint32_t* r, uint32_t addr) {
    asm volatile("ldmatrix.sync.aligned.m8n8.x4.trans.shared.b16 {%0,%1,%2,%3}, [%4];"
                 : "=r"(r[0]), "=r"(r[1]), "=r"(r[2]), "=r"(r[3]) : "r"(addr));
}
__device__ __forceinline__ void mma16816(float* d, const uint32_t* a, const uint32_t* b) {
    asm volatile(
        "mma.sync.aligned.m16n8k16.row.col.f32.bf16.bf16.f32 "
        "{%0,%1,%2,%3}, {%4,%5,%6,%7}, {%8,%9}, {%0,%1,%2,%3};"
        : "+f"(d[0]), "+f"(d[1]), "+f"(d[2]), "+f"(d[3])
        : "r"(a[0]), "r"(a[1]), "r"(a[2]), "r"(a[3]), "r"(b[0]), "r"(b[1]));
}
__device__ __forceinline__ void mma16816h(float* d, const uint32_t* a, const uint32_t* b) {
    asm volatile(
        "mma.sync.aligned.m16n8k16.row.col.f32.f16.f16.f32 "
        "{%0,%1,%2,%3}, {%4,%5,%6,%7}, {%8,%9}, {%0,%1,%2,%3};"
        : "+f"(d[0]), "+f"(d[1]), "+f"(d[2]), "+f"(d[3])
        : "r"(a[0]), "r"(a[1]), "r"(a[2]), "r"(a[3]), "r"(b[0]), "r"(b[1]));
}

// ===================== convert kernels =====================================
__global__ void conv_hilo(const float* __restrict__ src,
                          __nv_bfloat16* __restrict__ hi,
                          __nv_bfloat16* __restrict__ lo) {
    int i = blockIdx.x * 256 + threadIdx.x;
    float4 v = ((const float4*)src)[i];
    float f[4] = {v.x, v.y, v.z, v.w};
    __nv_bfloat16 h[4], l[4];
#pragma unroll
    for (int k = 0; k < 4; k++) {
        h[k] = __float2bfloat16(f[k]);
        l[k] = __float2bfloat16(f[k] - __bfloat162float(h[k]));
    }
    __nv_bfloat162 p0, p1, q0, q1;
    p0.x = h[0]; p0.y = h[1]; p1.x = h[2]; p1.y = h[3];
    q0.x = l[0]; q0.y = l[1]; q1.x = l[2]; q1.y = l[3];
    ((__nv_bfloat162*)hi)[i * 2] = p0; ((__nv_bfloat162*)hi)[i * 2 + 1] = p1;
    ((__nv_bfloat162*)lo)[i * 2] = q0; ((__nv_bfloat162*)lo)[i * 2 + 1] = q1;
}

__global__ void conv_w_t(const float* __restrict__ W0, const float* __restrict__ W1,
                         const float* __restrict__ W2, const float* __restrict__ W3,
                         const float* __restrict__ W4) {
    const float* Ws[5] = {W0, W1, W2, W3, W4};
    const float* W = Ws[blockIdx.z];
    __nv_bfloat16* hi = g_Wthi + (size_t)blockIdx.z * DIMm * DIMm;
    __nv_bfloat16* lo = g_Wtlo + (size_t)blockIdx.z * DIMm * DIMm;
    __shared__ float tile[32][33];
    int k0 = blockIdx.y * 32, n0 = blockIdx.x * 32;
    int c = threadIdx.x & 31, r8 = threadIdx.x >> 5;
#pragma unroll
    for (int i = 0; i < 4; i++) {
        int r = r8 + i * 8;
        tile[r][c] = W[(size_t)(k0 + r) * DIMm + n0 + c];
    }
    __syncthreads();
#pragma unroll
    for (int i = 0; i < 4; i++) {
        int r = r8 + i * 8;
        float v = tile[c][r];
        __nv_bfloat16 h = __float2bfloat16(v);
        hi[(size_t)(n0 + r) * DIMm + k0 + c] = h;
        lo[(size_t)(n0 + r) * DIMm + k0 + c] = __float2bfloat16(v - __bfloat162float(h));
    }
}

__global__ void hg_t(const float* __restrict__ W) {
    int idx = blockIdx.x * 256 + threadIdx.x;   // 16384
    int h = idx >> 10, k = idx & 1023;
    g_Whgt[idx] = W[k * 16 + h];
}

// ===================== HMMA projection/output GEMM =========================
__global__ __launch_bounds__(256)
void mma_gemm(const __nv_bfloat16* __restrict__ Ahi, const __nv_bfloat16* __restrict__ Alo,
              const __nv_bfloat16* __restrict__ WthiB, const __nv_bfloat16* __restrict__ WtloB,
              int wbase,
              float* __restrict__ C0, float* __restrict__ C1,
              float* __restrict__ C2, float* __restrict__ C3) {
    extern __shared__ __align__(1024) char smem[];
    uint32_t sbase = smem_u32(smem);
    int z = blockIdx.z;
    const __nv_bfloat16* Bh = WthiB + (size_t)(wbase + z) * DIMm * DIMm;
    const __nv_bfloat16* Bl = WtloB + (size_t)(wbase + z) * DIMm * DIMm;
    float* C = (z == 0) ? C0 : (z == 1) ? C1 : (z == 2) ? C2 : C3;

    int t = threadIdx.x;
    int lane = t & 31, w = t >> 5;
    int wm = w >> 2, wn = w & 3;
    int i0 = blockIdx.y * 128, n0 = blockIdx.x * 128;

    float acc[4][4][4] = {};

    int a_rl = ((lane >> 3) & 1) * 8 + (lane & 7);
    int a_ch = lane >> 4;
    int b_nl = (lane & 7) + ((lane >> 4) & 1) * 8;
    int b_ch = (lane >> 3) & 1;

    auto issue_load = [&](int ks) {
        uint32_t stage = sbase + (uint32_t)(ks & 1) * 32768u;
        int k0 = ks * 32;
#pragma unroll
        for (int i = 0; i < 8; i++) {
            int tile = i >> 1;
            int ci = ((i & 1) << 8) + t;
            int r = ci >> 2, c = ci & 3;
            const __nv_bfloat16* src = (tile == 0) ? Ahi : (tile == 1) ? Alo
                                     : (tile == 2) ? Bh : Bl;
            int rb = (tile < 2) ? i0 : n0;
            const __nv_bfloat16* g = src + (size_t)(rb + r) * DIMm + k0 + c * 8;
            uint32_t s = stage + (uint32_t)(tile * 8192 + r * 64 +
                          (((c ^ ((r >> 1) & 3))) << 4));
            cp_async16(s, g);
        }
        cp_commit();
    };

    issue_load(0);
    const int NS = DIMm / 32;
    for (int ks = 0; ks < NS; ks++) {
        if (ks + 1 < NS) issue_load(ks + 1);
        if (ks + 1 < NS) cp_wait1(); else cp_wait0();
        __syncthreads();
        uint32_t sb = sbase + (uint32_t)(ks & 1) * 32768u;
        uint32_t aH = sb, aL = sb + 8192, bH = sb + 16384, bL = sb + 24576;
#pragma unroll
        for (int kk = 0; kk < 2; kk++) {
            int c0 = kk * 2;
            uint32_t fBh[2][4], fBl[2][4], fA[4][4];
#pragma unroll
            for (int ng = 0; ng < 2; ng++) {
                int n = wn * 32 + ng * 16 + b_nl;
                int c = c0 + b_ch;
                uint32_t off = (uint32_t)(n * 64 + ((c ^ ((n >> 1) & 3)) << 4));
                ldsm_x4(fBh[ng], bH + off);
                ldsm_x4(fBl[ng], bL + off);
            }
#pragma unroll
            for (int mt = 0; mt < 4; mt++) {
                int r = wm * 64 + mt * 16 + a_rl;
                int c = c0 + a_ch;
                uint32_t off = (uint32_t)(r * 64 + ((c ^ ((r >> 1) & 3)) << 4));
                ldsm_x4(fA[mt], aH + off);
            }
#pragma unroll
            for (int mt = 0; mt < 4; mt++)
#pragma unroll
                for (int nt = 0; nt < 4; nt++) {
                    mma16816(acc[mt][nt], fA[mt], &fBh[nt >> 1][(nt & 1) * 2]);
                    mma16816(acc[mt][nt], fA[mt], &fBl[nt >> 1][(nt & 1) * 2]);
                }
#pragma unroll
            for (int mt = 0; mt < 4; mt++) {
                int r = wm * 64 + mt * 16 + a_rl;
                int c = c0 + a_ch;
                uint32_t off = (uint32_t)(r * 64 + ((c ^ ((r >> 1) & 3)) << 4));
                ldsm_x4(fA[mt], aL + off);
            }
#pragma unroll
            for (int mt = 0; mt < 4; mt++)
#pragma unroll
                for (int nt = 0; nt < 4; nt++)
                    mma16816(acc[mt][nt], fA[mt], &fBh[nt >> 1][(nt & 1) * 2]);
        }
        __syncthreads();
    }

    int row0 = i0 + wm * 64 + (lane >> 2);
    int col0 = n0 + wn * 32 + (lane & 3) * 2;
#pragma unroll
    for (int mt = 0; mt < 4; mt++)
#pragma unroll
        for (int nt = 0; nt < 4; nt++) {
            int r = row0 + mt * 16, cc = col0 + nt * 8;
            float2 v0 = {acc[mt][nt][0], acc[mt][nt][1]};
            float2 v1 = {acc[mt][nt][2], acc[mt][nt][3]};
            *(float2*)&C[(size_t)r * DIMm + cc] = v0;
            *(float2*)&C[(size_t)(r + 8) * DIMm + cc] = v1;
        }
}

// ---------------- head-gate: warp per row ----------------------------------
__global__ __launch_bounds__(128) void hgate_warp(const float* __restrict__ x) {
    int w = blockIdx.x * 4 + (threadIdx.x >> 5);
    int l = threadIdx.x & 31;
    float acc[16] = {};
    const float* xr = x + (size_t)w * 1024;
#pragma unroll
    for (int i = 0; i < 8; i++) {
        float4 xv = *(const float4*)&xr[i * 128 + l * 4];
#pragma unroll
        for (int h = 0; h < 16; h++) {
            float4 wv = *(const float4*)&g_Whgt[h * 1024 + i * 128 + l * 4];
            acc[h] += xv.x * wv.x + xv.y * wv.y + xv.z * wv.z + xv.w * wv.w;
        }
    }
#pragma unroll
    for (int h = 0; h < 16; h++)
#pragma unroll
        for (int o = 16; o > 0; o >>= 1) acc[h] += __shfl_xor_sync(~0u, acc[h], o);
    if (l == 0) {
#pragma unroll
        for (int h = 0; h < 16; h++) g_hgraw[(size_t)w * 16 + h] = acc[h];
    }
}

// ---------------- l2norm + scale + rope -> split layouts -------------------
__device__ __forceinline__ void wr_hl(__nv_bfloat16* H, __nv_bfloat16* L,
                                      size_t rowoff, int lane, float2 v) {
    __nv_bfloat16 hx = __float2bfloat16(v.x), hy = __float2bfloat16(v.y);
    __nv_bfloat162 hh; hh.x = hx; hh.y = hy;
    __nv_bfloat162 ll;
    ll.x = __float2bfloat16(v.x - __bfloat162float(hx));
    ll.y = __float2bfloat16(v.y - __bfloat162float(hy));
    ((__nv_bfloat162*)(H + rowoff))[lane] = hh;
    ((__nv_bfloat162*)(L + rowoff))[lane] = ll;
}
__device__ __forceinline__ void wr_hl16(__half* H, __half* L,
                                        size_t rowoff, int lane, float2 v) {
    __half hx = __float2half(v.x), hy = __float2half(v.y);
    __half2 hh; hh.x = hx; hh.y = hy;
    __half2 ll;
    ll.x = __float2half(v.x - __half2float(hx));
    ll.y = __float2half(v.y - __half2float(hy));
    ((__half2*)(H + rowoff))[lane] = hh;
    ((__half2*)(L + rowoff))[lane] = ll;
}

__global__ void prep_kernel(const float* __restrict__ freqs,
                            const float* __restrict__ q_scale,
                            const float* __restrict__ k_scale,
                            const float* __restrict__ mem_k,
                            const float* __restrict__ mem_v) {
    int w = (blockIdx.x * blockDim.x + threadIdx.x) >> 5;
    int lane = threadIdx.x & 31;
    const int MAIN = Bb * Nn * Hh;
    if (w < MAIN) {
        int b = w / (Nn * Hh); int r = w % (Nn * Hh);
        int n = r / Hh; int h = r % Hh;
        size_t src = (size_t)(b * Nn + n) * DIMm + h * DHh;
        float2 q2 = ((const float2*)&g_Qraw[src])[lane];
        float2 k2 = ((const float2*)&g_Kraw[src])[lane];
        float2 v2 = ((const float2*)&g_Vraw[src])[lane];
        float ssq = q2.x * q2.x + q2.y * q2.y;
        float ssk = k2.x * k2.x + k2.y * k2.y;
        for (int o = 16; o > 0; o >>= 1) {
            ssq += __shfl_xor_sync(~0u, ssq, o);
            ssk += __shfl_xor_sync(~0u, ssk, o);
        }
        float invq = 1.0f / fmaxf(sqrtf(ssq), 1e-12f);
        float invk = 1.0f / fmaxf(sqrtf(ssk), 1e-12f);
        float sqx = q_scale[h * DHh + 2 * lane], sqy = q_scale[h * DHh + 2 * lane + 1];
        float skx = k_scale[h * DHh + 2 * lane], sky = k_scale[h * DHh + 2 * lane + 1];
        float qx = q2.x * invq * sqx, qy = q2.y * invq * sqy;
        float kx = k2.x * invk * skx, ky = k2.y * invk * sky;
        float f = freqs[n * DHh + 2 * lane];
        float cf = cosf(f), sf = sinf(f);
        float2 qo = {qx * cf - qy * sf, qy * cf + qx * sf};
        float2 ko = {kx * cf - ky * sf, ky * cf + kx * sf};
        int bh = b * Hh + h;
        wr_hl(g_Qh, g_Ql, ((size_t)bh * Nn + n) * DHh, lane, qo);
        wr_hl(g_Kh, g_Kl, ((size_t)bh * PJ + Mm + n) * DHh, lane, ko);
        wr_hl16(g_Vh16, g_Vl16, ((size_t)bh * PJ + Mm + n) * DHh, lane, v2);
    } else {
        int w2 = w - MAIN;
        if (w2 < Bb * Hh * Mm) {
            int b = w2 / (Hh * Mm); int r = w2 % (Hh * Mm);
            int h = r / Mm; int m = r % Mm;
            float2 mk = ((const float2*)&mem_k[(size_t)(h * Mm + m) * DHh])[lane];
            float2 mv = ((const float2*)&mem_v[(size_t)(h * Mm + m) * DHh])[lane];
            float ss = mk.x * mk.x + mk.y * mk.y;
            for (int o = 16; o > 0; o >>= 1) ss += __shfl_xor_sync(~0u, ss, o);
            float inv = 1.0f / fmaxf(sqrtf(ss), 1e-12f);
            float2 ko = {mk.x * inv * k_scale[h * DHh + 2 * lane],
                         mk.y * inv * k_scale[h * DHh + 2 * lane + 1]};
            int bh = b * Hh + h;
            wr_hl(g_Kh, g_Kl, ((size_t)bh * PJ + m) * DHh, lane, ko);
            wr_hl16(g_Vh16, g_Vl16, ((size_t)bh * PJ + m) * DHh, lane, mv);
        }
    }
}

// ---------------- dots = Q K^T (HMMA bf16 hi/lo, raw scores) ---------------
__global__ __launch_bounds__(128) void dots_hmma() {
    int bh = blockIdx.z;
    int i0 = blockIdx.y * 64, j0 = blockIdx.x * 64;
    if (j0 >= i0 + 80) return;
    __shared__ __align__(128) char sm[32768];
    uint32_t sb = smem_u32(sm);
    int t = threadIdx.x, lane = t & 31, w = t >> 5;
    const __nv_bfloat16* Qh = g_Qh + ((size_t)bh * Nn + i0) * DHh;
    const __nv_bfloat16* Ql = g_Ql + ((size_t)bh * Nn + i0) * DHh;
    const __nv_bfloat16* Kh = g_Kh + ((size_t)bh * PJ + j0) * DHh;
    const __nv_bfloat16* Kl = g_Kl + ((size_t)bh * PJ + j0) * DHh;
#pragma unroll
    for (int i = 0; i < 16; i++) {
        int idx = t + i * 128;
        int tile = idx >> 9;
        int ci = idx & 511, r = ci >> 3, c = ci & 7;
        const __nv_bfloat16* src = (tile == 0) ? Qh : (tile == 1) ? Ql
                                 : (tile == 2) ? Kh : Kl;
        cp_async16(sb + tile * 8192 + r * 128 + ((c ^ (r & 7)) << 4),
                   src + (size_t)r * DHh + c * 8);
    }
    cp_commit(); cp_wait0();
    __syncthreads();
    int m0 = w * 16;
    float acc[8][4] = {};
    int a_r = m0 + ((lane >> 3) & 1) * 8 + (lane & 7);
    int a_c2 = lane >> 4;
    int b_r = (lane & 7) + ((lane >> 4) & 1) * 8;
    int b_c2 = (lane >> 3) & 1;
    uint32_t aH = sb, aL = sb + 8192, bH = sb + 16384, bL = sb + 24576;
#pragma unroll
    for (int pass = 0; pass < 3; pass++) {
        uint32_t at = (pass == 2) ? aL : aH;
        uint32_t bt = (pass == 1) ? bL : bH;
#pragma unroll
        for (int kk = 0; kk < 4; kk++) {
            uint32_t fA[4];
            int c = kk * 2 + a_c2;
            ldsm_x4(fA, at + a_r * 128 + ((c ^ (a_r & 7)) << 4));
#pragma unroll
            for (int ng = 0; ng < 4; ng++) {
                uint32_t fB[4];
                int n = ng * 16 + b_r;
                int cb = kk * 2 + b_c2;
                ldsm_x4(fB, bt + n * 128 + ((cb ^ (n & 7)) << 4));
                mma16816(acc[ng * 2], fA, fB);
                mma16816(acc[ng * 2 + 1], fA, fB + 2);
            }
        }
    }
    int row = i0 + m0 + (lane >> 2);
    int cb = (lane & 3) * 2;
    float* D = g_dots + (size_t)bh * Nn * NJ;
#pragma unroll
    for (int nb = 0; nb < 8; nb++) {
        int col = j0 + nb * 8 + cb;
        if (col < NJ) {
            float2 v0 = {acc[nb][0], acc[nb][1]};
            float2 v1 = {acc[nb][2], acc[nb][3]};
            *(float2*)&D[(size_t)row * NJ + col] = v0;
            *(float2*)&D[(size_t)(row + 8) * NJ + col] = v1;
        }
    }
}

// --- fused: pre-mix -> softmax -> post-mix -> fp16 P (512 thr, warp/head) --
__global__ __launch_bounds__(512) void softmax_kernel(const float* __restrict__ W_pre,
                                                      const float* __restrict__ W_post) {
    extern __shared__ float smemf[];
    float* sD = smemf;                 // 16 * NJ
    float* sT = sD + 16 * NJ;          // 16 * 128
    float* sWpre = sT + 16 * 128;      // 256
    float* sWpost = sWpre + 256;       // 256
    int t = threadIdx.x;
    int i = blockIdx.x, b = blockIdx.y;
    if (t < 256) { sWpre[t] = W_pre[t] * QK_SCALE; sWpost[t] = W_post[t]; }
    int jcount = i + 17;
    __syncthreads();
    int g = t >> 5, jslot = t & 31, lane = t & 31;

    // ---- pre-mix in 128-wide chunks ----
    for (int j0 = 0; j0 < jcount; j0 += 128) {
        {   // load 16h x 128j chunk (one float4 per thread)
            int h = t >> 5, jj = (t & 31) * 4;
            int j = j0 + jj;
            const float* src = &g_dots[((size_t)(b * Hh + h) * Nn + i) * NJ];
            float4 v = {0.f, 0.f, 0.f, 0.f};
            if (j + 3 < jcount) v = *(const float4*)&src[j];
            else {
                if (j < jcount)     v.x = src[j];
                if (j + 1 < jcount) v.y = src[j + 1];
                if (j + 2 < jcount) v.z = src[j + 2];
                if (j + 3 < jcount) v.w = src[j + 3];
            }
            *(float4*)&sT[h * 128 + jj] = v;
        }
        __syncthreads();
        int j = j0 + jslot * 4;
        if (j < jcount) {
            float4 a = {0.f, 0.f, 0.f, 0.f};
#pragma unroll
            for (int h = 0; h < 16; h++) {
                float wv = sWpre[g * 16 + h];
                float4 d = *(const float4*)&sT[h * 128 + jslot * 4];
                a.x += wv * d.x; a.y += wv * d.y;
                a.z += wv * d.z; a.w += wv * d.w;
            }
            if (j + 3 < jcount) *(float4*)&sD[g * NJ + j] = a;
            else {
                sD[g * NJ + j] = a.x;
                if (j + 1 < jcount) sD[g * NJ + j + 1] = a.y;
                if (j + 2 < jcount) sD[g * NJ + j + 2] = a.z;
            }
        }
        __syncthreads();
    }

    // ---- softmax: warp g owns head g ----
    {
        float* row = sD + g * NJ;
        float m = -FLT_MAX;
        for (int j = lane; j < jcount; j += 32) m = fmaxf(m, row[j]);
#pragma unroll
        for (int o = 16; o > 0; o >>= 1) m = fmaxf(m, __shfl_xor_sync(~0u, m, o));
        float l = 0.f;
        for (int j = lane; j < jcount; j += 32) {
            float e = __expf(row[j] - m); row[j] = e; l += e;
        }
#pragma unroll
        for (int o = 16; o > 0; o >>= 1) l += __shfl_xor_sync(~0u, l, o);
        float inv = 1.f / l;
        for (int j = lane; j < jcount; j += 32) row[j] *= inv;
    }
    __syncthreads();

    // ---- post-mix: warp g writes P row g (fp16), zero fill to i0+128 ----
    {
        int jendP = (i & ~63) + 128;
        __half* ph = g_P16 + ((size_t)(b * Hh + g) * Nn + i) * PJ;
        float wp[16];
#pragma unroll
        for (int h = 0; h < 16; h++) wp[h] = sWpost[g * 16 + h];
        for (int j = lane * 2; j < jendP; j += 64) {
            float2 a = {0.f, 0.f};
            if (j < jcount) {
#pragma unroll
                for (int h = 0; h < 16; h++) {
                    float2 d2 = *(const float2*)&sD[h * NJ + j];
                    a.x += wp[h] * d2.x;
                    a.y += wp[h] * d2.y;
                }
                if (j + 1 >= jcount) a.y = 0.f;
            }
            __half2 hh; hh.x = __float2half(a.x); hh.y = __float2half(a.y);
            ((__half2*)ph)[j >> 1] = hh;
        }
    }
}

// ------- O_g = P_g @ V_g (fp16: P single, V hi/lo; 2 passes) ---------------
__global__ __launch_bounds__(128) void av_hmma() {
    int bh = blockIdx.y;
    int i0 = blockIdx.x * 64;
    int ntiles = i0 / 64 + 2;
    extern __shared__ __align__(128) char sm[];   // 2 x 24576
    uint32_t sb = smem_u32(sm);
    int t = threadIdx.x, lane = t & 31, w = t >> 5;
    const __half* P = g_P16 + ((size_t)bh * Nn + i0) * PJ;
    const __half* Vh = g_Vh16 + (size_t)bh * PJ * DHh;
    const __half* Vl = g_Vl16 + (size_t)bh * PJ * DHh;

    auto issue = [&](int jt) {
        uint32_t st = sb + (uint32_t)(jt & 1) * 24576u;
#pragma unroll
        for (int i = 0; i < 12; i++) {
            int idx = t + i * 128;
            int tile = idx >> 9;
            int ci = idx & 511, r = ci >> 3, c = ci & 7;
            const __half* g;
            if (tile == 0)      g = P + (size_t)r * PJ + jt * 64 + c * 8;
            else if (tile == 1) g = Vh + (size_t)(jt * 64 + r) * DHh + c * 8;
            else                g = Vl + (size_t)(jt * 64 + r) * DHh + c * 8;
            cp_async16(st + tile * 8192 + r * 128 + ((c ^ (r & 7)) << 4), g);
        }
        cp_commit();
    };

    issue(0);
    float acc[8][4] = {};
    int m0 = w * 16;
    int a_r = m0 + ((lane >> 3) & 1) * 8 + (lane & 7);
    int a_c2 = lane >> 4;
    int v_j = (lane & 7) + ((lane >> 3) & 1) * 8;
    int v_c2 = lane >> 4;
    for (int jt = 0; jt < ntiles; jt++) {
        if (jt + 1 < ntiles) { issue(jt + 1); cp_wait1(); } else cp_wait0();
        __syncthreads();
        uint32_t st = sb + (uint32_t)(jt & 1) * 24576u;
        uint32_t pA = st, vH = st + 8192, vL = st + 16384;
#pragma unroll
        for (int kk = 0; kk < 4; kk++) {
            uint32_t fA[4];
            int c = kk * 2 + a_c2;
            ldsm_x4(fA, pA + a_r * 128 + ((c ^ (a_r & 7)) << 4));
#pragma unroll
            for (int dg = 0; dg < 4; dg++) {
                uint32_t fVh[4], fVl[4];
                int jr = kk * 16 + v_j;
                int cv = dg * 2 + v_c2;
                ldsm_x4_t(fVh, vH + jr * 128 + ((cv ^ (jr & 7)) << 4));
                ldsm_x4_t(fVl, vL + jr * 128 + ((cv ^ (jr & 7)) << 4));
                mma16816h(acc[dg * 2],     fA, fVh);
                mma16816h(acc[dg * 2 + 1], fA, fVh + 2);
                mma16816h(acc[dg * 2],     fA, fVl);
                mma16816h(acc[dg * 2 + 1], fA, fVl + 2);
            }
        }
        __syncthreads();
    }
    float* O = g_Ohd + ((size_t)bh * Nn + i0) * DHh;
    int row = m0 + (lane >> 2), cb = (lane & 3) * 2;
#pragma unroll
    for (int db = 0; db < 8; db++) {
        float2 v0 = {acc[db][0], acc[db][1]};
        float2 v1 = {acc[db][2], acc[db][3]};
        *(float2*)&O[(size_t)row * DHh + db * 8 + cb] = v0;
        *(float2*)&O[(size_t)(row + 8) * DHh + db * 8 + cb] = v1;
    }
}

// ------- gates only (post-mix already applied) -> bf16 hi/lo ---------------
__global__ __launch_bounds__(128) void mix_gate(const float* __restrict__ b_h,
                                                const float* __restrict__ b_v) {
    int rowid = blockIdx.x;             // 0..4095
    int b = rowid >> 10, n = rowid & 1023;
    int t = threadIdx.x;
#pragma unroll
    for (int k = 0; k < 8; k++) {
        int idx = t + k * 128; int g = idx >> 6, d = idx & 63;
        float a = g_Ohd[((size_t)(b * Hh + g) * Nn + n) * DHh + d];
        float hg = 1.f / (1.f + __expf(-(g_hgraw[(size_t)rowid * 16 + g] + b_h[g])));
        float vg = 1.f / (1.f + __expf(-(g_vgraw[(size_t)rowid * 1024 + idx] + b_v[idx])));
        float v = a * hg * vg;
        __nv_bfloat16 hi = __float2bfloat16(v);
        g_Ahi[(size_t)rowid * 1024 + idx] = hi;
        g_Alo[(size_t)rowid * 1024 + idx] = __float2bfloat16(v - __bfloat162float(hi));
    }
}

// ---------------------------------------------------------------------------
extern "C" void kernel_launch(void* const* d_in, const int* in_sizes, int n_in,
                              void* d_out, int out_size) {
    const float* x       = (const float*)d_in[0];
    const float* freqs   = (const float*)d_in[1];
    const float* Wq      = (const float*)d_in[2];
    const float* Wk      = (const float*)d_in[3];
    const float* Wv      = (const float*)d_in[4];
    const float* q_scale = (const float*)d_in[5];
    const float* k_scale = (const float*)d_in[6];
    const float* mem_k   = (const float*)d_in[7];
    const float* mem_v   = (const float*)d_in[8];
    const float* W_pre   = (const float*)d_in[9];
    const float* W_post  = (const float*)d_in[10];
    const float* W_hgate = (const float*)d_in[11];
    const float* b_hgate = (const float*)d_in[12];
    const float* W_vgate = (const float*)d_in[13];
    const float* b_vgate = (const float*)d_in[14];
    const float* Wo      = (const float*)d_in[15];
    float* out = (float*)d_out;

    float *Qraw, *Kraw, *Vraw, *vgraw;
    __nv_bfloat16 *Ahi, *Alo, *Wthi, *Wtlo;
    cudaGetSymbolAddress((void**)&Qraw, g_Qraw);
    cudaGetSymbolAddress((void**)&Kraw, g_Kraw);
    cudaGetSymbolAddress((void**)&Vraw, g_Vraw);
    cudaGetSymbolAddress((void**)&vgraw, g_vgraw);
    cudaGetSymbolAddress((void**)&Ahi, g_Ahi);
    cudaGetSymbolAddress((void**)&Alo, g_Alo);
    cudaGetSymbolAddress((void**)&Wthi, g_Wthi);
    cudaGetSymbolAddress((void**)&Wtlo, g_Wtlo);

    conv_hilo<<<ROWS * DIMm / 1024, 256>>>(x, Ahi, Alo);
    conv_w_t<<<dim3(32, 32, 5), 256>>>(Wq, Wk, Wv, W_vgate, Wo);
    hg_t<<<64, 256>>>(W_hgate);

    cudaFuncSetAttribute(mma_gemm, cudaFuncAttributeMaxDynamicSharedMemorySize, 65536);
    mma_gemm<<<dim3(DIMm / 128, ROWS / 128, 4), 256, 65536>>>(
        Ahi, Alo, Wthi, Wtlo, 0, Qraw, Kraw, Vraw, vgraw);
    hgate_warp<<<ROWS / 4, 128>>>(x);

    int warps = Bb * Nn * Hh + Bb * Hh * Mm;
    prep_kernel<<<(warps + 7) / 8, 256>>>(freqs, q_scale, k_scale, mem_k, mem_v);

    dots_hmma<<<dim3(17, 16, 64), 128>>>();

    size_t smem_bytes = (16 * NJ + 16 * 128 + 512) * sizeof(float);
    cudaFuncSetAttribute(softmax_kernel, cudaFuncAttributeMaxDynamicSharedMemorySize,
                         (int)smem_bytes);
    softmax_kernel<<<dim3(Nn, Bb), 512, smem_bytes>>>(W_pre, W_post);

    cudaFuncSetAttribute(av_hmma, cudaFuncAttributeMaxDynamicSharedMemorySize, 49152);
    av_hmma<<<dim3(16, 64), 128, 49152>>>();

    mix_gate<<<ROWS, 128>>>(b_hgate, b_vgate);

    mma_gemm<<<dim3(DIMm / 128, ROWS / 128, 1), 256, 65536>>>(
        Ahi, Alo, Wthi, Wtlo, 4, out, out, out, out);
}

// round 8
// speedup vs baseline: 4.9533x; 1.0026x over previous
#include <cuda_runtime.h>
#include <cuda_bf16.h>
#include <cuda_fp16.h>
#include <math.h>
#include <float.h>
#include <stdint.h>

#define Bb   4
#define Nn   1024
#define DIMm 1024
#define Hh   16
#define DHh  64
#define Mm   16
#define NJ   1040          // M + N
#define PJ   1088          // padded kv length (multiple of 64)
#define ROWS 4096          // B*N
#define QK_SCALE 10.0f

// ===================== scratch =============================================
__device__ float g_Qraw[(size_t)ROWS * DIMm];
__device__ float g_Kraw[(size_t)ROWS * DIMm];
__device__ float g_Vraw[(size_t)ROWS * DIMm];
__device__ float g_vgraw[(size_t)ROWS * DIMm];
__device__ float g_hgraw[(size_t)ROWS * Hh];
__device__ float g_dots[(size_t)64 * Nn * NJ];
__device__ float g_Ohd[(size_t)64 * Nn * DHh];
__device__ float g_Whgt[16 * 1024];
__device__ __nv_bfloat16 g_Qh[(size_t)64 * Nn * DHh];
__device__ __nv_bfloat16 g_Ql[(size_t)64 * Nn * DHh];
__device__ __nv_bfloat16 g_Kh[(size_t)64 * PJ * DHh];   // pad rows stay zero
__device__ __nv_bfloat16 g_Kl[(size_t)64 * PJ * DHh];
__device__ __half g_Vh16[(size_t)64 * PJ * DHh];        // pad rows stay zero
__device__ __half g_Vl16[(size_t)64 * PJ * DHh];
__device__ __half g_P16[(size_t)64 * Nn * PJ];
__device__ __nv_bfloat16 g_Ahi[(size_t)ROWS * DIMm];
__device__ __nv_bfloat16 g_Alo[(size_t)ROWS * DIMm];
__device__ __nv_bfloat16 g_Wthi[(size_t)5 * DIMm * DIMm];
__device__ __nv_bfloat16 g_Wtlo[(size_t)5 * DIMm * DIMm];

// ===================== PTX helpers (base ISA only) =========================
__device__ __forceinline__ uint32_t smem_u32(const void* p) {
    uint32_t a;
    asm("{ .reg .u64 tmp; cvta.to.shared.u64 tmp, %1; cvt.u32.u64 %0, tmp; }"
        : "=r"(a) : "l"(p));
    return a;
}
__device__ __forceinline__ void cp_async16(uint32_t s, const void* g) {
    asm volatile("cp.async.cg.shared.global [%0], [%1], 16;" :: "r"(s), "l"(g));
}
__device__ __forceinline__ void cp_commit() {
    asm volatile("cp.async.commit_group;" ::: "memory");
}
__device__ __forceinline__ void cp_wait2() {
    asm volatile("cp.async.wait_group 2;" ::: "memory");
}
__device__ __forceinline__ void cp_wait1() {
    asm volatile("cp.async.wait_group 1;" ::: "memory");
}
__device__ __forceinline__ void cp_wait0() {
    asm volatile("cp.async.wait_group 0;" ::: "memory");
}
__device__ __forceinline__ void ldsm_x4(uint32_t* r, uint32_t addr) {
    asm volatile("ldmatrix.sync.aligned.m8n8.x4.shared.b16 {%0,%1,%2,%3}, [%4];"
                 : "=r"(r[0]), "=r"(r[1]), "=r"(r[2]), "=r"(r[3]) : "r"(addr));
}
__device__ __forceinline__ void ldsm_x4_t(uint32_t* r, uint32_t addr) {
    asm volatile("ldmatrix.sync.aligned.m8n8.x4.trans.shared.b16 {%0,%1,%2,%3}, [%4];"
                 : "=r"(r[0]), "=r"(r[1]), "=r"(r[2]), "=r"(r[3]) : "r"(addr));
}
__device__ __forceinline__ void mma16816(float* d, const uint32_t* a, const uint32_t* b) {
    asm volatile(
        "mma.sync.aligned.m16n8k16.row.col.f32.bf16.bf16.f32 "
        "{%0,%1,%2,%3}, {%4,%5,%6,%7}, {%8,%9}, {%0,%1,%2,%3};"
        : "+f"(d[0]), "+f"(d[1]), "+f"(d[2]), "+f"(d[3])
        : "r"(a[0]), "r"(a[1]), "r"(a[2]), "r"(a[3]), "r"(b[0]), "r"(b[1]));
}
__device__ __forceinline__ void mma16816h(float* d, const uint32_t* a, const uint32_t* b) {
    asm volatile(
        "mma.sync.aligned.m16n8k16.row.col.f32.f16.f16.f32 "
        "{%0,%1,%2,%3}, {%4,%5,%6,%7}, {%8,%9}, {%0,%1,%2,%3};"
        : "+f"(d[0]), "+f"(d[1]), "+f"(d[2]), "+f"(d[3])
        : "r"(a[0]), "r"(a[1]), "r"(a[2]), "r"(a[3]), "r"(b[0]), "r"(b[1]));
}

// ===================== convert kernels =====================================
__global__ void conv_hilo(const float* __restrict__ src,
                          __nv_bfloat16* __restrict__ hi,
                          __nv_bfloat16* __restrict__ lo) {
    int i = blockIdx.x * 256 + threadIdx.x;
    float4 v = ((const float4*)src)[i];
    float f[4] = {v.x, v.y, v.z, v.w};
    __nv_bfloat16 h[4], l[4];
#pragma unroll
    for (int k = 0; k < 4; k++) {
        h[k] = __float2bfloat16(f[k]);
        l[k] = __float2bfloat16(f[k] - __bfloat162float(h[k]));
    }
    __nv_bfloat162 p0, p1, q0, q1;
    p0.x = h[0]; p0.y = h[1]; p1.x = h[2]; p1.y = h[3];
    q0.x = l[0]; q0.y = l[1]; q1.x = l[2]; q1.y = l[3];
    ((__nv_bfloat162*)hi)[i * 2] = p0; ((__nv_bfloat162*)hi)[i * 2 + 1] = p1;
    ((__nv_bfloat162*)lo)[i * 2] = q0; ((__nv_bfloat162*)lo)[i * 2 + 1] = q1;
}

__global__ void conv_w_t(const float* __restrict__ W0, const float* __restrict__ W1,
                         const float* __restrict__ W2, const float* __restrict__ W3,
                         const float* __restrict__ W4) {
    const float* Ws[5] = {W0, W1, W2, W3, W4};
    const float* W = Ws[blockIdx.z];
    __nv_bfloat16* hi = g_Wthi + (size_t)blockIdx.z * DIMm * DIMm;
    __nv_bfloat16* lo = g_Wtlo + (size_t)blockIdx.z * DIMm * DIMm;
    __shared__ float tile[32][33];
    int k0 = blockIdx.y * 32, n0 = blockIdx.x * 32;
    int c = threadIdx.x & 31, r8 = threadIdx.x >> 5;
#pragma unroll
    for (int i = 0; i < 4; i++) {
        int r = r8 + i * 8;
        tile[r][c] = W[(size_t)(k0 + r) * DIMm + n0 + c];
    }
    __syncthreads();
#pragma unroll
    for (int i = 0; i < 4; i++) {
        int r = r8 + i * 8;
        float v = tile[c][r];
        __nv_bfloat16 h = __float2bfloat16(v);
        hi[(size_t)(n0 + r) * DIMm + k0 + c] = h;
        lo[(size_t)(n0 + r) * DIMm + k0 + c] = __float2bfloat16(v - __bfloat162float(h));
    }
}

__global__ void hg_t(const float* __restrict__ W) {
    int idx = blockIdx.x * 256 + threadIdx.x;   // 16384
    int h = idx >> 10, k = idx & 1023;
    g_Whgt[idx] = W[k * 16 + h];
}

// ===================== HMMA projection/output GEMM (3-stage) ===============
__global__ __launch_bounds__(256)
void mma_gemm(const __nv_bfloat16* __restrict__ Ahi, const __nv_bfloat16* __restrict__ Alo,
              const __nv_bfloat16* __restrict__ WthiB, const __nv_bfloat16* __restrict__ WtloB,
              int wbase,
              float* __restrict__ C0, float* __restrict__ C1,
              float* __restrict__ C2, float* __restrict__ C3) {
    extern __shared__ __align__(1024) char smem[];
    uint32_t sbase = smem_u32(smem);
    int z = blockIdx.z;
    const __nv_bfloat16* Bh = WthiB + (size_t)(wbase + z) * DIMm * DIMm;
    const __nv_bfloat16* Bl = WtloB + (size_t)(wbase + z) * DIMm * DIMm;
    float* C = (z == 0) ? C0 : (z == 1) ? C1 : (z == 2) ? C2 : C3;

    int t = threadIdx.x;
    int lane = t & 31, w = t >> 5;
    int wm = w >> 2, wn = w & 3;
    int i0 = blockIdx.y * 128, n0 = blockIdx.x * 128;

    float acc[4][4][4] = {};

    int a_rl = ((lane >> 3) & 1) * 8 + (lane & 7);
    int a_ch = lane >> 4;
    int b_nl = (lane & 7) + ((lane >> 4) & 1) * 8;
    int b_ch = (lane >> 3) & 1;

    auto issue_load = [&](int ks) {
        uint32_t stage = sbase + (uint32_t)(ks % 3) * 32768u;
        int k0 = ks * 32;
#pragma unroll
        for (int i = 0; i < 8; i++) {
            int tile = i >> 1;
            int ci = ((i & 1) << 8) + t;
            int r = ci >> 2, c = ci & 3;
            const __nv_bfloat16* src = (tile == 0) ? Ahi : (tile == 1) ? Alo
                                     : (tile == 2) ? Bh : Bl;
            int rb = (tile < 2) ? i0 : n0;
            const __nv_bfloat16* g = src + (size_t)(rb + r) * DIMm + k0 + c * 8;
            uint32_t s = stage + (uint32_t)(tile * 8192 + r * 64 +
                          (((c ^ ((r >> 1) & 3))) << 4));
            cp_async16(s, g);
        }
        cp_commit();
    };

    issue_load(0);
    issue_load(1);
    const int NS = DIMm / 32;
    for (int ks = 0; ks < NS; ks++) {
        if (ks + 2 < NS) { issue_load(ks + 2); cp_wait2(); }
        else if (ks + 1 < NS) cp_wait1();
        else cp_wait0();
        __syncthreads();
        uint32_t sb = sbase + (uint32_t)(ks % 3) * 32768u;
        uint32_t aH = sb, aL = sb + 8192, bH = sb + 16384, bL = sb + 24576;
#pragma unroll
        for (int kk = 0; kk < 2; kk++) {
            int c0 = kk * 2;
            uint32_t fBh[2][4], fBl[2][4], fA[4][4];
#pragma unroll
            for (int ng = 0; ng < 2; ng++) {
                int n = wn * 32 + ng * 16 + b_nl;
                int c = c0 + b_ch;
                uint32_t off = (uint32_t)(n * 64 + ((c ^ ((n >> 1) & 3)) << 4));
                ldsm_x4(fBh[ng], bH + off);
                ldsm_x4(fBl[ng], bL + off);
            }
#pragma unroll
            for (int mt = 0; mt < 4; mt++) {
                int r = wm * 64 + mt * 16 + a_rl;
                int c = c0 + a_ch;
                uint32_t off = (uint32_t)(r * 64 + ((c ^ ((r >> 1) & 3)) << 4));
                ldsm_x4(fA[mt], aH + off);
            }
#pragma unroll
            for (int mt = 0; mt < 4; mt++)
#pragma unroll
                for (int nt = 0; nt < 4; nt++) {
                    mma16816(acc[mt][nt], fA[mt], &fBh[nt >> 1][(nt & 1) * 2]);
                    mma16816(acc[mt][nt], fA[mt], &fBl[nt >> 1][(nt & 1) * 2]);
                }
#pragma unroll
            for (int mt = 0; mt < 4; mt++) {
                int r = wm * 64 + mt * 16 + a_rl;
                int c = c0 + a_ch;
                uint32_t off = (uint32_t)(r * 64 + ((c ^ ((r >> 1) & 3)) << 4));
                ldsm_x4(fA[mt], aL + off);
            }
#pragma unroll
            for (int mt = 0; mt < 4; mt++)
#pragma unroll
                for (int nt = 0; nt < 4; nt++)
                    mma16816(acc[mt][nt], fA[mt], &fBh[nt >> 1][(nt & 1) * 2]);
        }
        __syncthreads();
    }

    int row0 = i0 + wm * 64 + (lane >> 2);
    int col0 = n0 + wn * 32 + (lane & 3) * 2;
#pragma unroll
    for (int mt = 0; mt < 4; mt++)
#pragma unroll
        for (int nt = 0; nt < 4; nt++) {
            int r = row0 + mt * 16, cc = col0 + nt * 8;
            float2 v0 = {acc[mt][nt][0], acc[mt][nt][1]};
            float2 v1 = {acc[mt][nt][2], acc[mt][nt][3]};
            *(float2*)&C[(size_t)r * DIMm + cc] = v0;
            *(float2*)&C[(size_t)(r + 8) * DIMm + cc] = v1;
        }
}

// ---------------- head-gate: warp per row ----------------------------------
__global__ __launch_bounds__(128) void hgate_warp(const float* __restrict__ x) {
    int w = blockIdx.x * 4 + (threadIdx.x >> 5);
    int l = threadIdx.x & 31;
    float acc[16] = {};
    const float* xr = x + (size_t)w * 1024;
#pragma unroll
    for (int i = 0; i < 8; i++) {
        float4 xv = *(const float4*)&xr[i * 128 + l * 4];
#pragma unroll
        for (int h = 0; h < 16; h++) {
            float4 wv = *(const float4*)&g_Whgt[h * 1024 + i * 128 + l * 4];
            acc[h] += xv.x * wv.x + xv.y * wv.y + xv.z * wv.z + xv.w * wv.w;
        }
    }
#pragma unroll
    for (int h = 0; h < 16; h++)
#pragma unroll
        for (int o = 16; o > 0; o >>= 1) acc[h] += __shfl_xor_sync(~0u, acc[h], o);
    if (l == 0) {
#pragma unroll
        for (int h = 0; h < 16; h++) g_hgraw[(size_t)w * 16 + h] = acc[h];
    }
}

// ---------------- l2norm + scale + rope -> split layouts -------------------
__device__ __forceinline__ void wr_hl(__nv_bfloat16* H, __nv_bfloat16* L,
                                      size_t rowoff, int lane, float2 v) {
    __nv_bfloat16 hx = __float2bfloat16(v.x), hy = __float2bfloat16(v.y);
    __nv_bfloat162 hh; hh.x = hx; hh.y = hy;
    __nv_bfloat162 ll;
    ll.x = __float2bfloat16(v.x - __bfloat162float(hx));
    ll.y = __float2bfloat16(v.y - __bfloat162float(hy));
    ((__nv_bfloat162*)(H + rowoff))[lane] = hh;
    ((__nv_bfloat162*)(L + rowoff))[lane] = ll;
}
__device__ __forceinline__ void wr_hl16(__half* H, __half* L,
                                        size_t rowoff, int lane, float2 v) {
    __half hx = __float2half(v.x), hy = __float2half(v.y);
    __half2 hh; hh.x = hx; hh.y = hy;
    __half2 ll;
    ll.x = __float2half(v.x - __half2float(hx));
    ll.y = __float2half(v.y - __half2float(hy));
    ((__half2*)(H + rowoff))[lane] = hh;
    ((__half2*)(L + rowoff))[lane] = ll;
}

__global__ void prep_kernel(const float* __restrict__ freqs,
                            const float* __restrict__ q_scale,
                            const float* __restrict__ k_scale,
                            const float* __restrict__ mem_k,
                            const float* __restrict__ mem_v) {
    int w = (blockIdx.x * blockDim.x + threadIdx.x) >> 5;
    int lane = threadIdx.x & 31;
    const int MAIN = Bb * Nn * Hh;
    if (w < MAIN) {
        int b = w / (Nn * Hh); int r = w % (Nn * Hh);
        int n = r / Hh; int h = r % Hh;
        size_t src = (size_t)(b * Nn + n) * DIMm + h * DHh;
        float2 q2 = ((const float2*)&g_Qraw[src])[lane];
        float2 k2 = ((const float2*)&g_Kraw[src])[lane];
        float2 v2 = ((const float2*)&g_Vraw[src])[lane];
        float ssq = q2.x * q2.x + q2.y * q2.y;
        float ssk = k2.x * k2.x + k2.y * k2.y;
        for (int o = 16; o > 0; o >>= 1) {
            ssq += __shfl_xor_sync(~0u, ssq, o);
            ssk += __shfl_xor_sync(~0u, ssk, o);
        }
        float invq = 1.0f / fmaxf(sqrtf(ssq), 1e-12f);
        float invk = 1.0f / fmaxf(sqrtf(ssk), 1e-12f);
        float sqx = q_scale[h * DHh + 2 * lane], sqy = q_scale[h * DHh + 2 * lane + 1];
        float skx = k_scale[h * DHh + 2 * lane], sky = k_scale[h * DHh + 2 * lane + 1];
        float qx = q2.x * invq * sqx, qy = q2.y * invq * sqy;
        float kx = k2.x * invk * skx, ky = k2.y * invk * sky;
        float f = freqs[n * DHh + 2 * lane];
        float cf = cosf(f), sf = sinf(f);
        float2 qo = {qx * cf - qy * sf, qy * cf + qx * sf};
        float2 ko = {kx * cf - ky * sf, ky * cf + kx * sf};
        int bh = b * Hh + h;
        wr_hl(g_Qh, g_Ql, ((size_t)bh * Nn + n) * DHh, lane, qo);
        wr_hl(g_Kh, g_Kl, ((size_t)bh * PJ + Mm + n) * DHh, lane, ko);
        wr_hl16(g_Vh16, g_Vl16, ((size_t)bh * PJ + Mm + n) * DHh, lane, v2);
    } else {
        int w2 = w - MAIN;
        if (w2 < Bb * Hh * Mm) {
            int b = w2 / (Hh * Mm); int r = w2 % (Hh * Mm);
            int h = r / Mm; int m = r % Mm;
            float2 mk = ((const float2*)&mem_k[(size_t)(h * Mm + m) * DHh])[lane];
            float2 mv = ((const float2*)&mem_v[(size_t)(h * Mm + m) * DHh])[lane];
            float ss = mk.x * mk.x + mk.y * mk.y;
            for (int o = 16; o > 0; o >>= 1) ss += __shfl_xor_sync(~0u, ss, o);
            float inv = 1.0f / fmaxf(sqrtf(ss), 1e-12f);
            float2 ko = {mk.x * inv * k_scale[h * DHh + 2 * lane],
                         mk.y * inv * k_scale[h * DHh + 2 * lane + 1]};
            int bh = b * Hh + h;
            wr_hl(g_Kh, g_Kl, ((size_t)bh * PJ + m) * DHh, lane, ko);
            wr_hl16(g_Vh16, g_Vl16, ((size_t)bh * PJ + m) * DHh, lane, mv);
        }
    }
}

// ---------------- dots = Q K^T (HMMA bf16 hi/lo, raw scores) ---------------
__global__ __launch_bounds__(128) void dots_hmma() {
    int bh = blockIdx.z;
    int i0 = blockIdx.y * 64, j0 = blockIdx.x * 64;
    if (j0 >= i0 + 80) return;
    __shared__ __align__(128) char sm[32768];
    uint32_t sb = smem_u32(sm);
    int t = threadIdx.x, lane = t & 31, w = t >> 5;
    const __nv_bfloat16* Qh = g_Qh + ((size_t)bh * Nn + i0) * DHh;
    const __nv_bfloat16* Ql = g_Ql + ((size_t)bh * Nn + i0) * DHh;
    const __nv_bfloat16* Kh = g_Kh + ((size_t)bh * PJ + j0) * DHh;
    const __nv_bfloat16* Kl = g_Kl + ((size_t)bh * PJ + j0) * DHh;
#pragma unroll
    for (int i = 0; i < 16; i++) {
        int idx = t + i * 128;
        int tile = idx >> 9;
        int ci = idx & 511, r = ci >> 3, c = ci & 7;
        const __nv_bfloat16* src = (tile == 0) ? Qh : (tile == 1) ? Ql
                                 : (tile == 2) ? Kh : Kl;
        cp_async16(sb + tile * 8192 + r * 128 + ((c ^ (r & 7)) << 4),
                   src + (size_t)r * DHh + c * 8);
    }
    cp_commit(); cp_wait0();
    __syncthreads();
    int m0 = w * 16;
    float acc[8][4] = {};
    int a_r = m0 + ((lane >> 3) & 1) * 8 + (lane & 7);
    int a_c2 = lane >> 4;
    int b_r = (lane & 7) + ((lane >> 4) & 1) * 8;
    int b_c2 = (lane >> 3) & 1;
    uint32_t aH = sb, aL = sb + 8192, bH = sb + 16384, bL = sb + 24576;
#pragma unroll
    for (int pass = 0; pass < 3; pass++) {
        uint32_t at = (pass == 2) ? aL : aH;
        uint32_t bt = (pass == 1) ? bL : bH;
#pragma unroll
        for (int kk = 0; kk < 4; kk++) {
            uint32_t fA[4];
            int c = kk * 2 + a_c2;
            ldsm_x4(fA, at + a_r * 128 + ((c ^ (a_r & 7)) << 4));
#pragma unroll
            for (int ng = 0; ng < 4; ng++) {
                uint32_t fB[4];
                int n = ng * 16 + b_r;
                int cb = kk * 2 + b_c2;
                ldsm_x4(fB, bt + n * 128 + ((cb ^ (n & 7)) << 4));
                mma16816(acc[ng * 2], fA, fB);
                mma16816(acc[ng * 2 + 1], fA, fB + 2);
            }
        }
    }
    int row = i0 + m0 + (lane >> 2);
    int cb = (lane & 3) * 2;
    float* D = g_dots + (size_t)bh * Nn * NJ;
#pragma unroll
    for (int nb = 0; nb < 8; nb++) {
        int col = j0 + nb * 8 + cb;
        if (col < NJ) {
            float2 v0 = {acc[nb][0], acc[nb][1]};
            float2 v1 = {acc[nb][2], acc[nb][3]};
            *(float2*)&D[(size_t)row * NJ + col] = v0;
            *(float2*)&D[(size_t)(row + 8) * NJ + col] = v1;
        }
    }
}

// --- fused: pre-mix -> softmax -> post-mix -> fp16 P (column-parallel) -----
__global__ __launch_bounds__(512) void softmax_kernel(const float* __restrict__ W_pre,
                                                      const float* __restrict__ W_post) {
    extern __shared__ float smemf[];
    float* sD = smemf;                 // 16 * NJ
    float* sWpre = sD + 16 * NJ;       // 256
    float* sWpost = sWpre + 256;       // 256
    int t = threadIdx.x;
    int i = blockIdx.x, b = blockIdx.y;
    if (t < 256) { sWpre[t] = W_pre[t] * QK_SCALE; sWpost[t] = W_post[t]; }
    int jcount = i + 17;
    int g = t >> 5, lane = t & 31;

    // ---- load all 16 rows (warp w owns head w), float4 coalesced ----
    {
        const float* src = &g_dots[((size_t)(b * Hh + g) * Nn + i) * NJ];
        float* dst = sD + g * NJ;
        for (int j = lane * 4; j < jcount; j += 128)
            *(float4*)&dst[j] = *(const float4*)&src[j];   // NJ=1040: in-bounds
    }
    __syncthreads();

    // ---- in-place pre-mix, column pairs ----
    for (int j = t * 2; j < jcount; j += 1024) {
        float2 col[16];
#pragma unroll
        for (int h = 0; h < 16; h++) col[h] = *(const float2*)&sD[h * NJ + j];
        float2 out[16];
#pragma unroll
        for (int gg = 0; gg < 16; gg++) {
            float ax = 0.f, ay = 0.f;
#pragma unroll
            for (int h = 0; h < 16; h++) {
                float wv = sWpre[gg * 16 + h];
                ax += wv * col[h].x; ay += wv * col[h].y;
            }
            out[gg].x = ax; out[gg].y = ay;
        }
#pragma unroll
        for (int gg = 0; gg < 16; gg++) *(float2*)&sD[gg * NJ + j] = out[gg];
    }
    __syncthreads();

    // ---- softmax: warp g owns head g ----
    {
        float* row = sD + g * NJ;
        float m = -FLT_MAX;
        for (int j = lane; j < jcount; j += 32) m = fmaxf(m, row[j]);
#pragma unroll
        for (int o = 16; o > 0; o >>= 1) m = fmaxf(m, __shfl_xor_sync(~0u, m, o));
        float l = 0.f;
        for (int j = lane; j < jcount; j += 32) {
            float e = __expf(row[j] - m); row[j] = e; l += e;
        }
#pragma unroll
        for (int o = 16; o > 0; o >>= 1) l += __shfl_xor_sync(~0u, l, o);
        float inv = 1.f / l;
        for (int j = lane; j < jcount; j += 32) row[j] *= inv;
    }
    __syncthreads();

    // ---- post-mix, column pairs, direct fp16 write (zero fill to i0+128) --
    int jendP = (i & ~63) + 128;
    size_t pbase = ((size_t)(b * Hh) * Nn + i) * PJ;   // + g2*Nn*PJ per head
    for (int j = t * 2; j < jendP; j += 1024) {
        __half2 outh[16];
        if (j < jcount) {
            float2 col[16];
#pragma unroll
            for (int h = 0; h < 16; h++) col[h] = *(const float2*)&sD[h * NJ + j];
            bool pairok = (j + 1 < jcount);
#pragma unroll
            for (int gg = 0; gg < 16; gg++) {
                float ax = 0.f, ay = 0.f;
#pragma unroll
                for (int h = 0; h < 16; h++) {
                    float wv = sWpost[gg * 16 + h];
                    ax += wv * col[h].x; ay += wv * col[h].y;
                }
                outh[gg].x = __float2half(ax);
                outh[gg].y = pairok ? __float2half(ay) : __float2half(0.f);
            }
        } else {
#pragma unroll
            for (int gg = 0; gg < 16; gg++) {
                outh[gg].x = __float2half(0.f); outh[gg].y = __float2half(0.f);
            }
        }
#pragma unroll
        for (int gg = 0; gg < 16; gg++)
            *(__half2*)&g_P16[pbase + (size_t)gg * Nn * PJ + j] = outh[gg];
    }
}

// ------- O_g = P_g @ V_g (fp16: P single, V hi/lo; 2 passes) ---------------
__global__ __launch_bounds__(128) void av_hmma() {
    int bh = blockIdx.y;
    int i0 = blockIdx.x * 64;
    int ntiles = i0 / 64 + 2;
    extern __shared__ __align__(128) char sm[];   // 2 x 24576
    uint32_t sb = smem_u32(sm);
    int t = threadIdx.x, lane = t & 31, w = t >> 5;
    const __half* P = g_P16 + ((size_t)bh * Nn + i0) * PJ;
    const __half* Vh = g_Vh16 + (size_t)bh * PJ * DHh;
    const __half* Vl = g_Vl16 + (size_t)bh * PJ * DHh;

    auto issue = [&](int jt) {
        uint32_t st = sb + (uint32_t)(jt & 1) * 24576u;
#pragma unroll
        for (int i = 0; i < 12; i++) {
            int idx = t + i * 128;
            int tile = idx >> 9;
            int ci = idx & 511, r = ci >> 3, c = ci & 7;
            const __half* g;
            if (tile == 0)      g = P + (size_t)r * PJ + jt * 64 + c * 8;
            else if (tile == 1) g = Vh + (size_t)(jt * 64 + r) * DHh + c * 8;
            else                g = Vl + (size_t)(jt * 64 + r) * DHh + c * 8;
            cp_async16(st + tile * 8192 + r * 128 + ((c ^ (r & 7)) << 4), g);
        }
        cp_commit();
    };

    issue(0);
    float acc[8][4] = {};
    int m0 = w * 16;
    int a_r = m0 + ((lane >> 3) & 1) * 8 + (lane & 7);
    int a_c2 = lane >> 4;
    int v_j = (lane & 7) + ((lane >> 3) & 1) * 8;
    int v_c2 = lane >> 4;
    for (int jt = 0; jt < ntiles; jt++) {
        if (jt + 1 < ntiles) { issue(jt + 1); cp_wait1(); } else cp_wait0();
        __syncthreads();
        uint32_t st = sb + (uint32_t)(jt & 1) * 24576u;
        uint32_t pA = st, vH = st + 8192, vL = st + 16384;
#pragma unroll
        for (int kk = 0; kk < 4; kk++) {
            uint32_t fA[4];
            int c = kk * 2 + a_c2;
            ldsm_x4(fA, pA + a_r * 128 + ((c ^ (a_r & 7)) << 4));
#pragma unroll
            for (int dg = 0; dg < 4; dg++) {
                uint32_t fVh[4], fVl[4];
                int jr = kk * 16 + v_j;
                int cv = dg * 2 + v_c2;
                ldsm_x4_t(fVh, vH + jr * 128 + ((cv ^ (jr & 7)) << 4));
                ldsm_x4_t(fVl, vL + jr * 128 + ((cv ^ (jr & 7)) << 4));
                mma16816h(acc[dg * 2],     fA, fVh);
                mma16816h(acc[dg * 2 + 1], fA, fVh + 2);
                mma16816h(acc[dg * 2],     fA, fVl);
                mma16816h(acc[dg * 2 + 1], fA, fVl + 2);
            }
        }
        __syncthreads();
    }
    float* O = g_Ohd + ((size_t)bh * Nn + i0) * DHh;
    int row = m0 + (lane >> 2), cb = (lane & 3) * 2;
#pragma unroll
    for (int db = 0; db < 8; db++) {
        float2 v0 = {acc[db][0], acc[db][1]};
        float2 v1 = {acc[db][2], acc[db][3]};
        *(float2*)&O[(size_t)row * DHh + db * 8 + cb] = v0;
        *(float2*)&O[(size_t)(row + 8) * DHh + db * 8 + cb] = v1;
    }
}

// ------- gates only (post-mix already applied) -> bf16 hi/lo ---------------
__global__ __launch_bounds__(128) void mix_gate(const float* __restrict__ b_h,
                                                const float* __restrict__ b_v) {
    int rowid = blockIdx.x;             // 0..4095
    int b = rowid >> 10, n = rowid & 1023;
    int t = threadIdx.x;
#pragma unroll
    for (int k = 0; k < 8; k++) {
        int idx = t + k * 128; int g = idx >> 6, d = idx & 63;
        float a = g_Ohd[((size_t)(b * Hh + g) * Nn + n) * DHh + d];
        float hg = 1.f / (1.f + __expf(-(g_hgraw[(size_t)rowid * 16 + g] + b_h[g])));
        float vg = 1.f / (1.f + __expf(-(g_vgraw[(size_t)rowid * 1024 + idx] + b_v[idx])));
        float v = a * hg * vg;
        __nv_bfloat16 hi = __float2bfloat16(v);
        g_Ahi[(size_t)rowid * 1024 + idx] = hi;
        g_Alo[(size_t)rowid * 1024 + idx] = __float2bfloat16(v - __bfloat162float(hi));
    }
}

// ---------------------------------------------------------------------------
extern "C" void kernel_launch(void* const* d_in, const int* in_sizes, int n_in,
                              void* d_out, int out_size) {
    const float* x       = (const float*)d_in[0];
    const float* freqs   = (const float*)d_in[1];
    const float* Wq      = (const float*)d_in[2];
    const float* Wk      = (const float*)d_in[3];
    const float* Wv      = (const float*)d_in[4];
    const float* q_scale = (const float*)d_in[5];
    const float* k_scale = (const float*)d_in[6];
    const float* mem_k   = (const float*)d_in[7];
    const float* mem_v   = (const float*)d_in[8];
    const float* W_pre   = (const float*)d_in[9];
    const float* W_post  = (const float*)d_in[10];
    const float* W_hgate = (const float*)d_in[11];
    const float* b_hgate = (const float*)d_in[12];
    const float* W_vgate = (const float*)d_in[13];
    const float* b_vgate = (const float*)d_in[14];
    const float* Wo      = (const float*)d_in[15];
    float* out = (float*)d_out;

    float *Qraw, *Kraw, *Vraw, *vgraw;
    __nv_bfloat16 *Ahi, *Alo, *Wthi, *Wtlo;
    cudaGetSymbolAddress((void**)&Qraw, g_Qraw);
    cudaGetSymbolAddress((void**)&Kraw, g_Kraw);
    cudaGetSymbolAddress((void**)&Vraw, g_Vraw);
    cudaGetSymbolAddress((void**)&vgraw, g_vgraw);
    cudaGetSymbolAddress((void**)&Ahi, g_Ahi);
    cudaGetSymbolAddress((void**)&Alo, g_Alo);
    cudaGetSymbolAddress((void**)&Wthi, g_Wthi);
    cudaGetSymbolAddress((void**)&Wtlo, g_Wtlo);

    conv_hilo<<<ROWS * DIMm / 1024, 256>>>(x, Ahi, Alo);
    conv_w_t<<<dim3(32, 32, 5), 256>>>(Wq, Wk, Wv, W_vgate, Wo);
    hg_t<<<64, 256>>>(W_hgate);

    cudaFuncSetAttribute(mma_gemm, cudaFuncAttributeMaxDynamicSharedMemorySize, 98304);
    mma_gemm<<<dim3(DIMm / 128, ROWS / 128, 4), 256, 98304>>>(
        Ahi, Alo, Wthi, Wtlo, 0, Qraw, Kraw, Vraw, vgraw);
    hgate_warp<<<ROWS / 4, 128>>>(x);

    int warps = Bb * Nn * Hh + Bb * Hh * Mm;
    prep_kernel<<<(warps + 7) / 8, 256>>>(freqs, q_scale, k_scale, mem_k, mem_v);

    dots_hmma<<<dim3(17, 16, 64), 128>>>();

    size_t smem_bytes = (16 * NJ + 512) * sizeof(float);
    cudaFuncSetAttribute(softmax_kernel, cudaFuncAttributeMaxDynamicSharedMemorySize,
                         (int)smem_bytes);
    softmax_kernel<<<dim3(Nn, Bb), 512, smem_bytes>>>(W_pre, W_post);

    cudaFuncSetAttribute(av_hmma, cudaFuncAttributeMaxDynamicSharedMemorySize, 49152);
    av_hmma<<<dim3(16, 64), 128, 49152>>>();

    mix_gate<<<ROWS, 128>>>(b_hgate, b_vgate);

    mma_gemm<<<dim3(DIMm / 128, ROWS / 128, 1), 256, 98304>>>(
        Ahi, Alo, Wthi, Wtlo, 4, out, out, out, out);
}